// round 2
// baseline (speedup 1.0000x reference)
#include <cuda_runtime.h>
#include <math.h>

// ---------------- constants (problem shapes are fixed) ----------------
#define B_   4
#define N_   4096
#define D_   256
#define H_   8
#define G_   8
#define DH_  64
#define INNER_ 512
#define M_   1024
#define OFFD_ 64
#define KS_  6

// ---------------- scratch ----------------
__device__ float g_q [B_ * N_ * INNER_];   // (B,N,512)  unscaled q, c = g*64+o
__device__ float g_pos[B_ * G_ * M_];      // sample positions
__device__ float g_k [B_ * M_ * INNER_];   // (B,M,512)
__device__ float g_v [B_ * M_ * INNER_];   // (B,M,512)
__device__ float g_ao[B_ * N_ * INNER_];   // attention output (B,N,512)

// ---------------- K1: q = grouped conv1x1 over cat(prev_x, x) ----------------
__global__ __launch_bounds__(256) void k_qproj(const float* __restrict__ x,
                                               const float* __restrict__ px,
                                               const float* __restrict__ wq) {
    int tok = blockIdx.x;                    // b*N + n
    __shared__ float sIn[512];
    int tid = threadIdx.x;
    sIn[tid]       = px[(size_t)tok * D_ + tid];       // channels 0..255 = prev
    sIn[tid + 256] = x [(size_t)tok * D_ + tid];       // channels 256..511 = x
    __syncthreads();
#pragma unroll
    for (int r = 0; r < 2; r++) {
        int oc = tid + r * 256;
        int g  = oc >> 6;
        const float* w  = wq + (size_t)oc * 64;
        const float* in = sIn + g * 64;
        float acc = 0.f;
#pragma unroll
        for (int i = 0; i < 64; i++) acc = fmaf(in[i], w[i], acc);
        g_q[(size_t)tok * INNER_ + oc] = acc;
    }
}

// ---------------- K2: offsets -> sampling positions ----------------
__global__ __launch_bounds__(256) void k_offsets(const float* __restrict__ w1,
                                                 const float* __restrict__ b1,
                                                 const float* __restrict__ w2) {
    int gid = blockIdx.x * blockDim.x + threadIdx.x;   // bc*M + m
    if (gid >= B_ * G_ * M_) return;
    int bc = gid >> 10, m = gid & (M_ - 1);
    int b = bc >> 3, g = bc & 7;
    const float* qbase = g_q + (size_t)b * N_ * INNER_ + g * 64;

    float hs[64];
#pragma unroll
    for (int c = 0; c < 64; c++) hs[c] = b1[c];

    int n_start = 4 * m - 1;
#pragma unroll
    for (int k = 0; k < KS_; k++) {
        int n = n_start + k;
        if (n >= 0 && n < N_) {
            const float* qrow = qbase + (size_t)n * INNER_;
#pragma unroll
            for (int c = 0; c < 64; c++) hs[c] = fmaf(qrow[c], w1[c * KS_ + k], hs[c]);
        }
    }
    float off_acc = 0.f;
#pragma unroll
    for (int c = 0; c < 64; c++) {
        float v  = hs[c];
        float ge = 0.5f * v * (1.f + erff(v * 0.70710678118654752f));   // exact GELU
        off_acc  = fmaf(ge, w2[c], off_acc);
    }
    float off = tanhf(off_acc) * 4.0f;                 // offset_scale = DS = 4
    float vg  = (float)m + off;
    // pos = ((vs+1)*N - 1)/2 with vs = 2*vg/(M-1) - 1  ==>  vg*N/(M-1) - 0.5
    g_pos[gid] = vg * ((float)N_ / (float)(M_ - 1)) - 0.5f;
}

// ---------------- K3: bilinear gather + k/v grouped conv1x1 ----------------
__global__ __launch_bounds__(128) void k_kv(const float* __restrict__ px,
                                            const float* __restrict__ wk,
                                            const float* __restrict__ wv) {
    int blk = blockIdx.x;                  // bc*M + m
    int m = blk & (M_ - 1);
    int bc = blk >> 10;
    int b = bc >> 3, g = bc & 7;
    __shared__ float skv[32];
    int tid = threadIdx.x;
    if (tid < 32) {
        float pos = g_pos[blk];
        float fp  = floorf(pos);
        int   i0  = (int)fp;
        float w1f = pos - fp;
        const float* base = px + (size_t)b * N_ * D_ + g * 32 + tid;
        float v0 = (i0 >= 0     && i0     < N_) ? base[(size_t)i0 * D_]       : 0.f;
        float v1 = (i0 + 1 >= 0 && i0 + 1 < N_) ? base[(size_t)(i0 + 1) * D_] : 0.f;
        skv[tid] = v0 * (1.f - w1f) + v1 * w1f;
    }
    __syncthreads();
    int o = tid & 63;
    const float* w = (tid < 64 ? wk : wv) + (size_t)(g * 64 + o) * 32;
    float acc = 0.f;
#pragma unroll
    for (int d = 0; d < 32; d++) acc = fmaf(skv[d], w[d], acc);
    float* dst = (tid < 64 ? g_k : g_v);
    dst[((size_t)b * M_ + m) * INNER_ + g * 64 + o] = acc;
}

// ---------------- K4: flash attention ----------------
#define ATTN_SMEM (4 * 64 * 68 * 4)
__global__ __launch_bounds__(256) void k_attn() {
    int blk = blockIdx.x;            // b*512 + h*64 + qt
    int qt = blk & 63;
    int h  = (blk >> 6) & 7;
    int b  = blk >> 9;
    int n0 = qt << 6;

    extern __shared__ float smem[];
    float (*sQ)[68] = (float(*)[68])(smem);
    float (*sK)[68] = (float(*)[68])(smem + 64 * 68);
    float (*sV)[68] = (float(*)[68])(smem + 2 * 64 * 68);
    float (*sS)[68] = (float(*)[68])(smem + 3 * 64 * 68);

    int tid = threadIdx.x;
    int ty = tid >> 4, tx = tid & 15;

    const float* qsrc = g_q + ((size_t)b * N_ + n0) * INNER_ + h * 64;
    for (int idx = tid; idx < 64 * 64; idx += 256) {
        int r = idx >> 6, d = idx & 63;
        sQ[r][d] = qsrc[(size_t)r * INNER_ + d] * 0.125f;   // SCALE = 1/sqrt(64)
    }

    float acc[4][4];
    float rmax[4], rsum[4];
#pragma unroll
    for (int i = 0; i < 4; i++) {
        rmax[i] = -1e30f; rsum[i] = 0.f;
#pragma unroll
        for (int j = 0; j < 4; j++) acc[i][j] = 0.f;
    }

    const float* kbase = g_k + ((size_t)b * M_) * INNER_ + h * 64;
    const float* vbase = g_v + ((size_t)b * M_) * INNER_ + h * 64;
    __syncthreads();

    for (int kt = 0; kt < 16; kt++) {
        int m0 = kt << 6;
        for (int idx = tid; idx < 64 * 64; idx += 256) {
            int r = idx >> 6, d = idx & 63;
            sK[r][d] = kbase[(size_t)(m0 + r) * INNER_ + d];
            sV[r][d] = vbase[(size_t)(m0 + r) * INNER_ + d];
        }
        __syncthreads();

        float s[4][4];
#pragma unroll
        for (int i = 0; i < 4; i++)
#pragma unroll
            for (int j = 0; j < 4; j++) s[i][j] = 0.f;

#pragma unroll
        for (int d0 = 0; d0 < 64; d0 += 4) {
            float4 qv[4], kv[4];
#pragma unroll
            for (int i = 0; i < 4; i++) qv[i] = *(const float4*)&sQ[ty * 4 + i][d0];
#pragma unroll
            for (int j = 0; j < 4; j++) kv[j] = *(const float4*)&sK[tx * 4 + j][d0];
#pragma unroll
            for (int i = 0; i < 4; i++)
#pragma unroll
                for (int j = 0; j < 4; j++) {
                    s[i][j] = fmaf(qv[i].x, kv[j].x, s[i][j]);
                    s[i][j] = fmaf(qv[i].y, kv[j].y, s[i][j]);
                    s[i][j] = fmaf(qv[i].z, kv[j].z, s[i][j]);
                    s[i][j] = fmaf(qv[i].w, kv[j].w, s[i][j]);
                }
        }

        // online softmax (row state replicated across the 16 tx lanes)
#pragma unroll
        for (int i = 0; i < 4; i++) {
            float lm = fmaxf(fmaxf(s[i][0], s[i][1]), fmaxf(s[i][2], s[i][3]));
            lm = fmaxf(lm, __shfl_xor_sync(0xffffffffu, lm, 1));
            lm = fmaxf(lm, __shfl_xor_sync(0xffffffffu, lm, 2));
            lm = fmaxf(lm, __shfl_xor_sync(0xffffffffu, lm, 4));
            lm = fmaxf(lm, __shfl_xor_sync(0xffffffffu, lm, 8));
            float nm = fmaxf(rmax[i], lm);
            float f  = __expf(rmax[i] - nm);
            rmax[i]  = nm;
            float ls = 0.f;
#pragma unroll
            for (int j = 0; j < 4; j++) {
                float p = __expf(s[i][j] - nm);
                ls += p;
                sS[ty * 4 + i][tx * 4 + j] = p;
            }
            ls += __shfl_xor_sync(0xffffffffu, ls, 1);
            ls += __shfl_xor_sync(0xffffffffu, ls, 2);
            ls += __shfl_xor_sync(0xffffffffu, ls, 4);
            ls += __shfl_xor_sync(0xffffffffu, ls, 8);
            rsum[i] = rsum[i] * f + ls;
#pragma unroll
            for (int j = 0; j < 4; j++) acc[i][j] *= f;
        }
        __syncthreads();

        // P @ V
#pragma unroll 8
        for (int kj = 0; kj < 64; kj++) {
            float4 vv = *(const float4*)&sV[kj][tx * 4];
#pragma unroll
            for (int i = 0; i < 4; i++) {
                float p = sS[ty * 4 + i][kj];
                acc[i][0] = fmaf(p, vv.x, acc[i][0]);
                acc[i][1] = fmaf(p, vv.y, acc[i][1]);
                acc[i][2] = fmaf(p, vv.z, acc[i][2]);
                acc[i][3] = fmaf(p, vv.w, acc[i][3]);
            }
        }
        __syncthreads();
    }

    float* dst = g_ao + ((size_t)b * N_ + n0) * INNER_ + h * 64;
#pragma unroll
    for (int i = 0; i < 4; i++) {
        float inv = 1.f / rsum[i];
#pragma unroll
        for (int j = 0; j < 4; j++)
            dst[(size_t)(ty * 4 + i) * INNER_ + tx * 4 + j] = acc[i][j] * inv;
    }
}

// ---------------- K5: output projection (16384 x 256 x 512) + bias ----------------
__global__ __launch_bounds__(256) void k_oproj(const float* __restrict__ wo,
                                               const float* __restrict__ bo,
                                               float* __restrict__ out) {
    __shared__ float As[64][33];
    __shared__ float Wt[32][68];   // 68*4=272B row stride -> float4-aligned
    int row0 = blockIdx.x * 64;
    int o0   = blockIdx.y * 64;
    int tid  = threadIdx.x;
    int ty = tid >> 4, tx = tid & 15;

    float acc[4][4];
#pragma unroll
    for (int i = 0; i < 4; i++)
#pragma unroll
        for (int j = 0; j < 4; j++) acc[i][j] = 0.f;

    for (int c0 = 0; c0 < INNER_; c0 += 32) {
#pragma unroll
        for (int t = 0; t < 8; t++) {
            int idx = tid + t * 256;
            int r = idx >> 5, cc = idx & 31;
            As[r][cc] = g_ao[(size_t)(row0 + r) * INNER_ + c0 + cc];
            Wt[cc][r] = wo[(size_t)(o0 + r) * INNER_ + c0 + cc];
        }
        __syncthreads();
#pragma unroll
        for (int cc = 0; cc < 32; cc++) {
            float av[4];
#pragma unroll
            for (int i = 0; i < 4; i++) av[i] = As[ty * 4 + i][cc];
            float4 wv = *(const float4*)&Wt[cc][tx * 4];
#pragma unroll
            for (int i = 0; i < 4; i++) {
                acc[i][0] = fmaf(av[i], wv.x, acc[i][0]);
                acc[i][1] = fmaf(av[i], wv.y, acc[i][1]);
                acc[i][2] = fmaf(av[i], wv.z, acc[i][2]);
                acc[i][3] = fmaf(av[i], wv.w, acc[i][3]);
            }
        }
        __syncthreads();
    }
#pragma unroll
    for (int i = 0; i < 4; i++)
#pragma unroll
        for (int j = 0; j < 4; j++) {
            int o = o0 + tx * 4 + j;
            out[(size_t)(row0 + ty * 4 + i) * D_ + o] = acc[i][j] + bo[o];
        }
}

// ---------------- launch ----------------
extern "C" void kernel_launch(void* const* d_in, const int* in_sizes, int n_in,
                              void* d_out, int out_size) {
    const float* x      = (const float*)d_in[0];
    const float* prev_x = (const float*)d_in[1];
    const float* wq     = (const float*)d_in[2];
    const float* wk     = (const float*)d_in[3];
    const float* wv     = (const float*)d_in[4];
    const float* wo     = (const float*)d_in[5];
    const float* bo     = (const float*)d_in[6];
    const float* w_off1 = (const float*)d_in[7];
    const float* b_off1 = (const float*)d_in[8];
    const float* w_off2 = (const float*)d_in[9];
    float* out = (float*)d_out;

    cudaFuncSetAttribute(k_attn, cudaFuncAttributeMaxDynamicSharedMemorySize, ATTN_SMEM);

    k_qproj  <<<B_ * N_, 256>>>(x, prev_x, wq);
    k_offsets<<<(B_ * G_ * M_) / 256, 256>>>(w_off1, b_off1, w_off2);
    k_kv     <<<B_ * G_ * M_, 128>>>(prev_x, wk, wv);
    k_attn   <<<B_ * H_ * (N_ / 64), 256, ATTN_SMEM>>>();
    k_oproj  <<<dim3((B_ * N_) / 64, D_ / 64), 256>>>(wo, bo, out);
}

// round 4
// speedup vs baseline: 2.6203x; 2.6203x over previous
#include <cuda_runtime.h>
#include <math.h>

// ---------------- constants (problem shapes are fixed) ----------------
#define B_   4
#define N_   4096
#define D_   256
#define H_   8
#define G_   8
#define DH_  64
#define INNER_ 512
#define M_   1024
#define KS_  6

// ---------------- scratch ----------------
__device__ float g_q [B_ * N_ * INNER_];   // (B,N,512)  unscaled q, c = g*64+o
__device__ float g_pos[B_ * G_ * M_];      // sample positions
__device__ float g_k [B_ * M_ * INNER_];   // (B,M,512)
__device__ float g_v [B_ * M_ * INNER_];   // (B,M,512)
__device__ float g_ao[B_ * N_ * INNER_];   // attention output (B,N,512)

// ---------------- K1: q = grouped conv1x1, GEMM-tiled per group ----------------
__global__ __launch_bounds__(256) void k_qproj(const float* __restrict__ x,
                                               const float* __restrict__ px,
                                               const float* __restrict__ wq) {
    __shared__ float sIn[64][68];
    __shared__ float sW [64][68];
    int tok0 = blockIdx.x * 64;
    int g    = blockIdx.y;
    int tid  = threadIdx.x;
    int ty = tid >> 4, tx = tid & 15;

    const float* src = (g < 4) ? px : x;
    int cb = (g & 3) * 64;

#pragma unroll
    for (int it = 0; it < 4; it++) {
        int idx = tid + it * 256;          // 1024 float4 slots
        int r = idx >> 4, c4 = (idx & 15) * 4;
        float4 a = *(const float4*)&src[(size_t)(tok0 + r) * D_ + cb + c4];
        *(float4*)&sIn[r][c4] = a;
        float4 w = *(const float4*)&wq[(size_t)(g * 64 + r) * 64 + c4];
        *(float4*)&sW[r][c4] = w;
    }
    __syncthreads();

    float acc[4][4];
#pragma unroll
    for (int i = 0; i < 4; i++)
#pragma unroll
        for (int j = 0; j < 4; j++) acc[i][j] = 0.f;

#pragma unroll
    for (int d0 = 0; d0 < 64; d0 += 4) {
        float4 av[4], wv[4];
#pragma unroll
        for (int i = 0; i < 4; i++) av[i] = *(const float4*)&sIn[ty + 16 * i][d0];
#pragma unroll
        for (int j = 0; j < 4; j++) wv[j] = *(const float4*)&sW[tx + 16 * j][d0];
#pragma unroll
        for (int i = 0; i < 4; i++)
#pragma unroll
            for (int j = 0; j < 4; j++) {
                acc[i][j] = fmaf(av[i].x, wv[j].x, acc[i][j]);
                acc[i][j] = fmaf(av[i].y, wv[j].y, acc[i][j]);
                acc[i][j] = fmaf(av[i].z, wv[j].z, acc[i][j]);
                acc[i][j] = fmaf(av[i].w, wv[j].w, acc[i][j]);
            }
    }
#pragma unroll
    for (int i = 0; i < 4; i++)
#pragma unroll
        for (int j = 0; j < 4; j++)
            g_q[(size_t)(tok0 + ty + 16 * i) * INNER_ + g * 64 + tx + 16 * j] = acc[i][j];
}

// ---------------- K2: offsets -> sampling positions ----------------
// 4 positions per block; 64 threads per position (channel per thread)
__global__ __launch_bounds__(256) void k_offsets(const float* __restrict__ w1,
                                                 const float* __restrict__ b1,
                                                 const float* __restrict__ w2) {
    __shared__ float red[8];
    int tid = threadIdx.x;
    int p = blockIdx.x * 4 + (tid >> 6);     // bc*M + m
    int c = tid & 63;
    int bc = p >> 10, m = p & (M_ - 1);
    int b = bc >> 3, g = bc & 7;
    const float* qbase = g_q + (size_t)b * N_ * INNER_ + g * 64 + c;

    float h = b1[c];
    int n0 = 4 * m - 1;
#pragma unroll
    for (int k = 0; k < KS_; k++) {
        int n = n0 + k;
        if (n >= 0 && n < N_) h = fmaf(qbase[(size_t)n * INNER_], w1[c * KS_ + k], h);
    }
    float ge  = 0.5f * h * (1.f + erff(h * 0.70710678118654752f));   // exact GELU
    float val = ge * w2[c];
#pragma unroll
    for (int o = 16; o > 0; o >>= 1) val += __shfl_xor_sync(0xffffffffu, val, o);
    if ((tid & 31) == 0) red[tid >> 5] = val;
    __syncthreads();
    if (tid < 4) {
        float off = tanhf(red[2 * tid] + red[2 * tid + 1]) * 4.0f;   // offset_scale = DS
        int pp = blockIdx.x * 4 + tid;
        int mm = pp & (M_ - 1);
        g_pos[pp] = ((float)mm + off) * ((float)N_ / (float)(M_ - 1)) - 0.5f;
    }
}

// ---------------- K3: bilinear gather + k/v grouped conv1x1 ----------------
__global__ __launch_bounds__(128) void k_kv(const float* __restrict__ px,
                                            const float* __restrict__ wk,
                                            const float* __restrict__ wv) {
    int blk = blockIdx.x;                  // bc*M + m
    int m = blk & (M_ - 1);
    int bc = blk >> 10;
    int b = bc >> 3, g = bc & 7;
    __shared__ float skv[32];
    int tid = threadIdx.x;
    if (tid < 32) {
        float pos = g_pos[blk];
        float fp  = floorf(pos);
        int   i0  = (int)fp;
        float w1f = pos - fp;
        const float* base = px + (size_t)b * N_ * D_ + g * 32 + tid;
        float v0 = (i0 >= 0     && i0     < N_) ? base[(size_t)i0 * D_]       : 0.f;
        float v1 = (i0 + 1 >= 0 && i0 + 1 < N_) ? base[(size_t)(i0 + 1) * D_] : 0.f;
        skv[tid] = v0 * (1.f - w1f) + v1 * w1f;
    }
    __syncthreads();
    int o = tid & 63;
    const float* w = (tid < 64 ? wk : wv) + (size_t)(g * 64 + o) * 32;
    float acc = 0.f;
#pragma unroll
    for (int d = 0; d < 32; d++) acc = fmaf(skv[d], w[d], acc);
    float* dst = (tid < 64 ? g_k : g_v);
    dst[((size_t)b * M_ + m) * INNER_ + g * 64 + o] = acc;
}

// ---------------- K4: flash attention (bank-conflict-free mapping) ----------------
#define ATTN_SMEM (3 * 64 * 68 * 4)
__global__ __launch_bounds__(256) void k_attn() {
    int blk = blockIdx.x;            // b*512 + h*64 + qt
    int qt = blk & 63;
    int h  = (blk >> 6) & 7;
    int b  = blk >> 9;
    int n0 = qt << 6;

    extern __shared__ float smem[];
    float (*sQ) [68] = (float(*)[68])(smem);
    float (*sKS)[68] = (float(*)[68])(smem + 64 * 68);      // K, then aliased as P
    float (*sV) [68] = (float(*)[68])(smem + 2 * 64 * 68);

    int tid = threadIdx.x;
    int ty = tid >> 4, tx = tid & 15;

    const float* qsrc = g_q + ((size_t)b * N_ + n0) * INNER_ + h * 64;
#pragma unroll
    for (int it = 0; it < 4; it++) {
        int idx = tid + it * 256;
        int r = idx >> 4, c4 = (idx & 15) * 4;
        float4 qv = *(const float4*)&qsrc[(size_t)r * INNER_ + c4];
        qv.x *= 0.125f; qv.y *= 0.125f; qv.z *= 0.125f; qv.w *= 0.125f;
        *(float4*)&sQ[r][c4] = qv;
    }

    float acc[4][4];
    float rmax[4], rsum[4];
#pragma unroll
    for (int i = 0; i < 4; i++) {
        rmax[i] = -1e30f; rsum[i] = 0.f;
#pragma unroll
        for (int j = 0; j < 4; j++) acc[i][j] = 0.f;
    }

    const float* kbase = g_k + ((size_t)b * M_) * INNER_ + h * 64;
    const float* vbase = g_v + ((size_t)b * M_) * INNER_ + h * 64;
    __syncthreads();

    for (int kt = 0; kt < 16; kt++) {
        int m0 = kt << 6;
#pragma unroll
        for (int it = 0; it < 4; it++) {
            int idx = tid + it * 256;
            int r = idx >> 4, c4 = (idx & 15) * 4;
            *(float4*)&sKS[r][c4] = *(const float4*)&kbase[(size_t)(m0 + r) * INNER_ + c4];
            *(float4*)&sV [r][c4] = *(const float4*)&vbase[(size_t)(m0 + r) * INNER_ + c4];
        }
        __syncthreads();

        float s[4][4];
#pragma unroll
        for (int i = 0; i < 4; i++)
#pragma unroll
            for (int j = 0; j < 4; j++) s[i][j] = 0.f;

#pragma unroll
        for (int d0 = 0; d0 < 64; d0 += 4) {
            float4 qv[4], kv[4];
#pragma unroll
            for (int i = 0; i < 4; i++) qv[i] = *(const float4*)&sQ [ty + 16 * i][d0];
#pragma unroll
            for (int j = 0; j < 4; j++) kv[j] = *(const float4*)&sKS[tx + 16 * j][d0];
#pragma unroll
            for (int i = 0; i < 4; i++)
#pragma unroll
                for (int j = 0; j < 4; j++) {
                    s[i][j] = fmaf(qv[i].x, kv[j].x, s[i][j]);
                    s[i][j] = fmaf(qv[i].y, kv[j].y, s[i][j]);
                    s[i][j] = fmaf(qv[i].z, kv[j].z, s[i][j]);
                    s[i][j] = fmaf(qv[i].w, kv[j].w, s[i][j]);
                }
        }
        __syncthreads();   // K reads done; sKS becomes P

        // online softmax; row r = ty+16i is replicated across the 16 tx lanes
#pragma unroll
        for (int i = 0; i < 4; i++) {
            float lm = fmaxf(fmaxf(s[i][0], s[i][1]), fmaxf(s[i][2], s[i][3]));
            lm = fmaxf(lm, __shfl_xor_sync(0xffffffffu, lm, 1));
            lm = fmaxf(lm, __shfl_xor_sync(0xffffffffu, lm, 2));
            lm = fmaxf(lm, __shfl_xor_sync(0xffffffffu, lm, 4));
            lm = fmaxf(lm, __shfl_xor_sync(0xffffffffu, lm, 8));
            float nm = fmaxf(rmax[i], lm);
            float f  = __expf(rmax[i] - nm);
            rmax[i]  = nm;
            float ls = 0.f;
#pragma unroll
            for (int j = 0; j < 4; j++) {
                float p = __expf(s[i][j] - nm);
                ls += p;
                sKS[ty + 16 * i][tx + 16 * j] = p;
            }
            ls += __shfl_xor_sync(0xffffffffu, ls, 1);
            ls += __shfl_xor_sync(0xffffffffu, ls, 2);
            ls += __shfl_xor_sync(0xffffffffu, ls, 4);
            ls += __shfl_xor_sync(0xffffffffu, ls, 8);
            rsum[i] = rsum[i] * f + ls;
#pragma unroll
            for (int j = 0; j < 4; j++) acc[i][j] *= f;
        }
        __syncthreads();

        // P @ V   (acc col = tx*4+j for float4 V loads)
#pragma unroll 8
        for (int kj = 0; kj < 64; kj++) {
            float4 vv = *(const float4*)&sV[kj][tx * 4];
#pragma unroll
            for (int i = 0; i < 4; i++) {
                float p = sKS[ty + 16 * i][kj];
                acc[i][0] = fmaf(p, vv.x, acc[i][0]);
                acc[i][1] = fmaf(p, vv.y, acc[i][1]);
                acc[i][2] = fmaf(p, vv.z, acc[i][2]);
                acc[i][3] = fmaf(p, vv.w, acc[i][3]);
            }
        }
        __syncthreads();
    }

    float* dst = g_ao + ((size_t)b * N_ + n0) * INNER_ + h * 64;
#pragma unroll
    for (int i = 0; i < 4; i++) {
        float inv = 1.f / rsum[i];
        float4 o4 = make_float4(acc[i][0] * inv, acc[i][1] * inv,
                                acc[i][2] * inv, acc[i][3] * inv);
        *(float4*)&dst[(size_t)(ty + 16 * i) * INNER_ + tx * 4] = o4;
    }
}

// ---------------- K5: output projection (16384 x 256 x 512) + bias ----------------
__global__ __launch_bounds__(256) void k_oproj(const float* __restrict__ wo,
                                               const float* __restrict__ bo,
                                               float* __restrict__ out) {
    __shared__ float As[64][33];
    __shared__ float Wt[32][68];
    int row0 = blockIdx.x * 64;
    int o0   = blockIdx.y * 64;
    int tid  = threadIdx.x;
    int ty = tid >> 4, tx = tid & 15;

    float acc[4][4];
#pragma unroll
    for (int i = 0; i < 4; i++)
#pragma unroll
        for (int j = 0; j < 4; j++) acc[i][j] = 0.f;

    for (int c0 = 0; c0 < INNER_; c0 += 32) {
#pragma unroll
        for (int t = 0; t < 8; t++) {
            int idx = tid + t * 256;
            int r = idx >> 5, cc = idx & 31;
            As[r][cc] = g_ao[(size_t)(row0 + r) * INNER_ + c0 + cc];
            Wt[cc][r] = wo[(size_t)(o0 + r) * INNER_ + c0 + cc];
        }
        __syncthreads();
#pragma unroll
        for (int cc = 0; cc < 32; cc++) {
            float av[4];
#pragma unroll
            for (int i = 0; i < 4; i++) av[i] = As[ty * 4 + i][cc];
            float4 wv = *(const float4*)&Wt[cc][tx * 4];
#pragma unroll
            for (int i = 0; i < 4; i++) {
                acc[i][0] = fmaf(av[i], wv.x, acc[i][0]);
                acc[i][1] = fmaf(av[i], wv.y, acc[i][1]);
                acc[i][2] = fmaf(av[i], wv.z, acc[i][2]);
                acc[i][3] = fmaf(av[i], wv.w, acc[i][3]);
            }
        }
        __syncthreads();
    }
#pragma unroll
    for (int i = 0; i < 4; i++)
#pragma unroll
        for (int j = 0; j < 4; j++) {
            int o = o0 + tx * 4 + j;
            out[(size_t)(row0 + ty * 4 + i) * D_ + o] = acc[i][j] + bo[o];
        }
}

// ---------------- launch ----------------
extern "C" void kernel_launch(void* const* d_in, const int* in_sizes, int n_in,
                              void* d_out, int out_size) {
    const float* x      = (const float*)d_in[0];
    const float* prev_x = (const float*)d_in[1];
    const float* wq     = (const float*)d_in[2];
    const float* wk     = (const float*)d_in[3];
    const float* wv     = (const float*)d_in[4];
    const float* wo     = (const float*)d_in[5];
    const float* bo     = (const float*)d_in[6];
    const float* w_off1 = (const float*)d_in[7];
    const float* b_off1 = (const float*)d_in[8];
    const float* w_off2 = (const float*)d_in[9];
    float* out = (float*)d_out;

    cudaFuncSetAttribute(k_attn, cudaFuncAttributeMaxDynamicSharedMemorySize, ATTN_SMEM);

    k_qproj  <<<dim3(B_ * N_ / 64, G_), 256>>>(x, prev_x, wq);
    k_offsets<<<(B_ * G_ * M_) / 4, 256>>>(w_off1, b_off1, w_off2);   // 8192 blocks, 4 pos each
    k_kv     <<<B_ * G_ * M_, 128>>>(prev_x, wk, wv);
    k_attn   <<<B_ * H_ * (N_ / 64), 256, ATTN_SMEM>>>();
    k_oproj  <<<dim3((B_ * N_) / 64, D_ / 64), 256>>>(wo, bo, out);
}

// round 5
// speedup vs baseline: 2.7533x; 1.0508x over previous
#include <cuda_runtime.h>
#include <math.h>

// ---------------- constants (problem shapes are fixed) ----------------
#define B_   4
#define N_   4096
#define D_   256
#define H_   8
#define G_   8
#define DH_  64
#define INNER_ 512
#define M_   1024
#define KS_  6

// ---------------- f32x2 packed helpers (Blackwell FFMA2) ----------------
__device__ __forceinline__ unsigned long long pk2(float a, float b) {
    unsigned long long r;
    asm("mov.b64 %0, {%1, %2};" : "=l"(r) : "f"(a), "f"(b));
    return r;
}
__device__ __forceinline__ void upk2(float& a, float& b, unsigned long long r) {
    asm("mov.b64 {%0, %1}, %2;" : "=f"(a), "=f"(b) : "l"(r));
}
__device__ __forceinline__ void ffma2(unsigned long long& d,
                                      unsigned long long a, unsigned long long b) {
    asm("fma.rn.f32x2 %0, %1, %2, %0;" : "+l"(d) : "l"(a), "l"(b));
}
__device__ __forceinline__ void fmul2(unsigned long long& d, unsigned long long a) {
    asm("mul.rn.f32x2 %0, %0, %1;" : "+l"(d) : "l"(a));
}

// ---------------- scratch ----------------
__device__ float g_q [B_ * N_ * INNER_];   // (B,N,512)
__device__ float g_pos[B_ * G_ * M_];
__device__ float g_k [B_ * M_ * INNER_];
__device__ float g_v [B_ * M_ * INNER_];
__device__ float g_ao[B_ * N_ * INNER_];

// ---------------- K1: q = grouped conv1x1, GEMM-tiled per group ----------------
__global__ __launch_bounds__(256) void k_qproj(const float* __restrict__ x,
                                               const float* __restrict__ px,
                                               const float* __restrict__ wq) {
    __shared__ float sIn[64][68];
    __shared__ float sW [64][68];
    int tok0 = blockIdx.x * 64;
    int g    = blockIdx.y;
    int tid  = threadIdx.x;
    int ty = tid >> 4, tx = tid & 15;

    const float* src = (g < 4) ? px : x;
    int cb = (g & 3) * 64;

#pragma unroll
    for (int it = 0; it < 4; it++) {
        int idx = tid + it * 256;
        int r = idx >> 4, c4 = (idx & 15) * 4;
        *(float4*)&sIn[r][c4] = *(const float4*)&src[(size_t)(tok0 + r) * D_ + cb + c4];
        *(float4*)&sW [r][c4] = *(const float4*)&wq [(size_t)(g * 64 + r) * 64 + c4];
    }
    __syncthreads();

    float acc[4][4];
#pragma unroll
    for (int i = 0; i < 4; i++)
#pragma unroll
        for (int j = 0; j < 4; j++) acc[i][j] = 0.f;

#pragma unroll
    for (int d0 = 0; d0 < 64; d0 += 4) {
        float4 av[4], wv[4];
#pragma unroll
        for (int i = 0; i < 4; i++) av[i] = *(const float4*)&sIn[ty + 16 * i][d0];
#pragma unroll
        for (int j = 0; j < 4; j++) wv[j] = *(const float4*)&sW[tx + 16 * j][d0];
#pragma unroll
        for (int i = 0; i < 4; i++)
#pragma unroll
            for (int j = 0; j < 4; j++) {
                acc[i][j] = fmaf(av[i].x, wv[j].x, acc[i][j]);
                acc[i][j] = fmaf(av[i].y, wv[j].y, acc[i][j]);
                acc[i][j] = fmaf(av[i].z, wv[j].z, acc[i][j]);
                acc[i][j] = fmaf(av[i].w, wv[j].w, acc[i][j]);
            }
    }
#pragma unroll
    for (int i = 0; i < 4; i++)
#pragma unroll
        for (int j = 0; j < 4; j++)
            g_q[(size_t)(tok0 + ty + 16 * i) * INNER_ + g * 64 + tx + 16 * j] = acc[i][j];
}

// ---------------- K2: offsets -> sampling positions ----------------
__global__ __launch_bounds__(256) void k_offsets(const float* __restrict__ w1,
                                                 const float* __restrict__ b1,
                                                 const float* __restrict__ w2) {
    __shared__ float red[8];
    int tid = threadIdx.x;
    int p = blockIdx.x * 4 + (tid >> 6);
    int c = tid & 63;
    int bc = p >> 10, m = p & (M_ - 1);
    int b = bc >> 3, g = bc & 7;
    const float* qbase = g_q + (size_t)b * N_ * INNER_ + g * 64 + c;

    float h = b1[c];
    int n0 = 4 * m - 1;
#pragma unroll
    for (int k = 0; k < KS_; k++) {
        int n = n0 + k;
        if (n >= 0 && n < N_) h = fmaf(qbase[(size_t)n * INNER_], w1[c * KS_ + k], h);
    }
    float ge  = 0.5f * h * (1.f + erff(h * 0.70710678118654752f));
    float val = ge * w2[c];
#pragma unroll
    for (int o = 16; o > 0; o >>= 1) val += __shfl_xor_sync(0xffffffffu, val, o);
    if ((tid & 31) == 0) red[tid >> 5] = val;
    __syncthreads();
    if (tid < 4) {
        float off = tanhf(red[2 * tid] + red[2 * tid + 1]) * 4.0f;
        int pp = blockIdx.x * 4 + tid;
        int mm = pp & (M_ - 1);
        g_pos[pp] = ((float)mm + off) * ((float)N_ / (float)(M_ - 1)) - 0.5f;
    }
}

// ---------------- K3: bilinear gather + k/v grouped conv1x1 ----------------
__global__ __launch_bounds__(128) void k_kv(const float* __restrict__ px,
                                            const float* __restrict__ wk,
                                            const float* __restrict__ wv) {
    int blk = blockIdx.x;
    int m = blk & (M_ - 1);
    int bc = blk >> 10;
    int b = bc >> 3, g = bc & 7;
    __shared__ float skv[32];
    int tid = threadIdx.x;
    if (tid < 32) {
        float pos = g_pos[blk];
        float fp  = floorf(pos);
        int   i0  = (int)fp;
        float w1f = pos - fp;
        const float* base = px + (size_t)b * N_ * D_ + g * 32 + tid;
        float v0 = (i0 >= 0     && i0     < N_) ? base[(size_t)i0 * D_]       : 0.f;
        float v1 = (i0 + 1 >= 0 && i0 + 1 < N_) ? base[(size_t)(i0 + 1) * D_] : 0.f;
        skv[tid] = v0 * (1.f - w1f) + v1 * w1f;
    }
    __syncthreads();
    int o = tid & 63;
    const float* w = (tid < 64 ? wk : wv) + (size_t)(g * 64 + o) * 32;
    float acc = 0.f;
#pragma unroll
    for (int d = 0; d < 32; d++) acc = fmaf(skv[d], w[d], acc);
    float* dst = (tid < 64 ? g_k : g_v);
    dst[((size_t)b * M_ + m) * INNER_ + g * 64 + o] = acc;
}

// ---------------- K4: flash attention, BQ=128, BK=64, 8x4 tiles, FFMA2 ----------------
// smem: Q[128][68] | K[64][68] | V[64][68] | P[128][68]
#define ATTN_SMEM ((128 + 64 + 64 + 128) * 68 * 4)
__global__ __launch_bounds__(256) void k_attn() {
    int blk = blockIdx.x;            // b*256 + h*32 + qt
    int qt = blk & 31;
    int h  = (blk >> 5) & 7;
    int b  = blk >> 8;
    int n0 = qt << 7;

    extern __shared__ float smem[];
    float (*sQ)[68] = (float(*)[68])(smem);
    float (*sK)[68] = (float(*)[68])(smem + 128 * 68);
    float (*sV)[68] = (float(*)[68])(smem + (128 + 64) * 68);
    float (*sP)[68] = (float(*)[68])(smem + (128 + 128) * 68);

    int tid = threadIdx.x;
    int ty = tid >> 4, tx = tid & 15;

    const float* qsrc = g_q + ((size_t)b * N_ + n0) * INNER_ + h * 64;
#pragma unroll
    for (int it = 0; it < 8; it++) {           // 128x16 float4 chunks
        int idx = tid + it * 256;
        int r = idx >> 4, c4 = (idx & 15) * 4;
        float4 qv = *(const float4*)&qsrc[(size_t)r * INNER_ + c4];
        qv.x *= 0.125f; qv.y *= 0.125f; qv.z *= 0.125f; qv.w *= 0.125f;
        *(float4*)&sQ[r][c4] = qv;
    }

    unsigned long long acc2[8][2];
    float rmax[8], rsum[8];
#pragma unroll
    for (int i = 0; i < 8; i++) {
        rmax[i] = -1e30f; rsum[i] = 0.f;
        acc2[i][0] = 0ull; acc2[i][1] = 0ull;
    }

    const float* kbase = g_k + ((size_t)b * M_) * INNER_ + h * 64;
    const float* vbase = g_v + ((size_t)b * M_) * INNER_ + h * 64;
    __syncthreads();

    for (int kt = 0; kt < 16; kt++) {
        int m0 = kt << 6;
#pragma unroll
        for (int it = 0; it < 4; it++) {       // 64x16 chunks each for K and V
            int idx = tid + it * 256;
            int r = idx >> 4, c4 = (idx & 15) * 4;
            *(float4*)&sK[r][c4] = *(const float4*)&kbase[(size_t)(m0 + r) * INNER_ + c4];
            *(float4*)&sV[r][c4] = *(const float4*)&vbase[(size_t)(m0 + r) * INNER_ + c4];
        }
        __syncthreads();

        // ---- QK^T : packed pairs along d ----
        unsigned long long s2[8][4];
#pragma unroll
        for (int i = 0; i < 8; i++)
#pragma unroll
            for (int j = 0; j < 4; j++) s2[i][j] = 0ull;

#pragma unroll 4
        for (int d0 = 0; d0 < 64; d0 += 4) {   // one float4 = two d-pairs
            ulonglong2 q2[8], k2[4];
#pragma unroll
            for (int i = 0; i < 8; i++) q2[i] = *(const ulonglong2*)&sQ[ty + 16 * i][d0];
#pragma unroll
            for (int j = 0; j < 4; j++) k2[j] = *(const ulonglong2*)&sK[tx + 16 * j][d0];
#pragma unroll
            for (int i = 0; i < 8; i++)
#pragma unroll
                for (int j = 0; j < 4; j++) {
                    ffma2(s2[i][j], q2[i].x, k2[j].x);
                    ffma2(s2[i][j], q2[i].y, k2[j].y);
                }
        }
        __syncthreads();   // K consumed (sK idle until next tile)

        // ---- online softmax over 8 rows ----
#pragma unroll
        for (int i = 0; i < 8; i++) {
            float s[4];
#pragma unroll
            for (int j = 0; j < 4; j++) {
                float lo, hi; upk2(lo, hi, s2[i][j]);
                s[j] = lo + hi;
            }
            float lm = fmaxf(fmaxf(s[0], s[1]), fmaxf(s[2], s[3]));
            lm = fmaxf(lm, __shfl_xor_sync(0xffffffffu, lm, 1));
            lm = fmaxf(lm, __shfl_xor_sync(0xffffffffu, lm, 2));
            lm = fmaxf(lm, __shfl_xor_sync(0xffffffffu, lm, 4));
            lm = fmaxf(lm, __shfl_xor_sync(0xffffffffu, lm, 8));
            float nm = fmaxf(rmax[i], lm);
            float f  = __expf(rmax[i] - nm);
            rmax[i]  = nm;
            float ls = 0.f;
#pragma unroll
            for (int j = 0; j < 4; j++) {
                float p = __expf(s[j] - nm);
                ls += p;
                sP[ty + 16 * i][tx + 16 * j] = p;
            }
            ls += __shfl_xor_sync(0xffffffffu, ls, 1);
            ls += __shfl_xor_sync(0xffffffffu, ls, 2);
            ls += __shfl_xor_sync(0xffffffffu, ls, 4);
            ls += __shfl_xor_sync(0xffffffffu, ls, 8);
            rsum[i] = rsum[i] * f + ls;
            unsigned long long f2 = pk2(f, f);
            fmul2(acc2[i][0], f2);
            fmul2(acc2[i][1], f2);
        }
        __syncthreads();

        // ---- P @ V : packed pairs along output d, p duplicated ----
#pragma unroll 4
        for (int kg = 0; kg < 16; kg++) {      // groups of 4 kj
            float4 pv[8];
#pragma unroll
            for (int i = 0; i < 8; i++) pv[i] = *(const float4*)&sP[ty + 16 * i][kg * 4];
            ulonglong2 v2[4];
#pragma unroll
            for (int jj = 0; jj < 4; jj++) v2[jj] = *(const ulonglong2*)&sV[kg * 4 + jj][tx * 4];
#pragma unroll
            for (int jj = 0; jj < 4; jj++)
#pragma unroll
                for (int i = 0; i < 8; i++) {
                    float p = (jj == 0) ? pv[i].x : (jj == 1) ? pv[i].y
                            : (jj == 2) ? pv[i].z : pv[i].w;
                    unsigned long long p2 = pk2(p, p);
                    ffma2(acc2[i][0], p2, v2[jj].x);
                    ffma2(acc2[i][1], p2, v2[jj].y);
                }
        }
        __syncthreads();
    }

    float* dst = g_ao + ((size_t)b * N_ + n0) * INNER_ + h * 64;
#pragma unroll
    for (int i = 0; i < 8; i++) {
        float inv = 1.f / rsum[i];
        float a0, a1, a2, a3;
        upk2(a0, a1, acc2[i][0]);
        upk2(a2, a3, acc2[i][1]);
        float4 o4 = make_float4(a0 * inv, a1 * inv, a2 * inv, a3 * inv);
        *(float4*)&dst[(size_t)(ty + 16 * i) * INNER_ + tx * 4] = o4;
    }
}

// ---------------- K5: output projection 16384x256x512, 8x4 tiles, FFMA2 ----------------
// smem: A[128][68] | W[64][68]
#define OPROJ_SMEM ((128 + 64) * 68 * 4)
__global__ __launch_bounds__(256) void k_oproj(const float* __restrict__ wo,
                                               const float* __restrict__ bo,
                                               float* __restrict__ out) {
    extern __shared__ float smem[];
    float (*sA)[68] = (float(*)[68])(smem);
    float (*sW)[68] = (float(*)[68])(smem + 128 * 68);
    int row0 = blockIdx.x * 128;
    int o0   = blockIdx.y * 64;
    int tid  = threadIdx.x;
    int ty = tid >> 4, tx = tid & 15;

    unsigned long long c2[8][4];
#pragma unroll
    for (int i = 0; i < 8; i++)
#pragma unroll
        for (int j = 0; j < 4; j++) c2[i][j] = 0ull;

    for (int c0 = 0; c0 < INNER_; c0 += 64) {
#pragma unroll
        for (int it = 0; it < 8; it++) {       // A: 128x16 chunks
            int idx = tid + it * 256;
            int r = idx >> 4, c4 = (idx & 15) * 4;
            *(float4*)&sA[r][c4] = *(const float4*)&g_ao[(size_t)(row0 + r) * INNER_ + c0 + c4];
        }
#pragma unroll
        for (int it = 0; it < 4; it++) {       // W: 64x16 chunks
            int idx = tid + it * 256;
            int r = idx >> 4, c4 = (idx & 15) * 4;
            *(float4*)&sW[r][c4] = *(const float4*)&wo[(size_t)(o0 + r) * INNER_ + c0 + c4];
        }
        __syncthreads();
#pragma unroll 4
        for (int d0 = 0; d0 < 64; d0 += 4) {
            ulonglong2 a2[8], w2[4];
#pragma unroll
            for (int i = 0; i < 8; i++) a2[i] = *(const ulonglong2*)&sA[ty + 16 * i][d0];
#pragma unroll
            for (int j = 0; j < 4; j++) w2[j] = *(const ulonglong2*)&sW[tx + 16 * j][d0];
#pragma unroll
            for (int i = 0; i < 8; i++)
#pragma unroll
                for (int j = 0; j < 4; j++) {
                    ffma2(c2[i][j], a2[i].x, w2[j].x);
                    ffma2(c2[i][j], a2[i].y, w2[j].y);
                }
        }
        __syncthreads();
    }
#pragma unroll
    for (int i = 0; i < 8; i++)
#pragma unroll
        for (int j = 0; j < 4; j++) {
            float lo, hi; upk2(lo, hi, c2[i][j]);
            int o = o0 + tx + 16 * j;
            out[(size_t)(row0 + ty + 16 * i) * D_ + o] = lo + hi + bo[o];
        }
}

// ---------------- launch ----------------
extern "C" void kernel_launch(void* const* d_in, const int* in_sizes, int n_in,
                              void* d_out, int out_size) {
    const float* x      = (const float*)d_in[0];
    const float* prev_x = (const float*)d_in[1];
    const float* wq     = (const float*)d_in[2];
    const float* wk     = (const float*)d_in[3];
    const float* wv     = (const float*)d_in[4];
    const float* wo     = (const float*)d_in[5];
    const float* bo     = (const float*)d_in[6];
    const float* w_off1 = (const float*)d_in[7];
    const float* b_off1 = (const float*)d_in[8];
    const float* w_off2 = (const float*)d_in[9];
    float* out = (float*)d_out;

    cudaFuncSetAttribute(k_attn,  cudaFuncAttributeMaxDynamicSharedMemorySize, ATTN_SMEM);
    cudaFuncSetAttribute(k_oproj, cudaFuncAttributeMaxDynamicSharedMemorySize, OPROJ_SMEM);

    k_qproj  <<<dim3(B_ * N_ / 64, G_), 256>>>(x, prev_x, wq);
    k_offsets<<<(B_ * G_ * M_) / 4, 256>>>(w_off1, b_off1, w_off2);
    k_kv     <<<B_ * G_ * M_, 128>>>(prev_x, wk, wv);
    k_attn   <<<B_ * H_ * (N_ / 128), 256, ATTN_SMEM>>>();
    k_oproj  <<<dim3((B_ * N_) / 128, D_ / 64), 256, OPROJ_SMEM>>>(wo, bo, out);
}

// round 6
// speedup vs baseline: 4.4117x; 1.6023x over previous
#include <cuda_runtime.h>
#include <math.h>
#include <stdint.h>

// ---------------- constants (problem shapes are fixed) ----------------
#define B_   4
#define N_   4096
#define D_   256
#define H_   8
#define G_   8
#define DH_  64
#define INNER_ 512
#define M_   1024
#define KS_  6

// ---------------- f32x2 packed helpers (kept for k_oproj) ----------------
__device__ __forceinline__ void upk2(float& a, float& b, unsigned long long r) {
    asm("mov.b64 {%0, %1}, %2;" : "=f"(a), "=f"(b) : "l"(r));
}
__device__ __forceinline__ void ffma2(unsigned long long& d,
                                      unsigned long long a, unsigned long long b) {
    asm("fma.rn.f32x2 %0, %1, %2, %0;" : "+l"(d) : "l"(a), "l"(b));
}

// ---------------- tf32 mma helpers ----------------
__device__ __forceinline__ uint32_t f2tf32(float f) {
    uint32_t r; asm("cvt.rna.tf32.f32 %0, %1;" : "=r"(r) : "f"(f)); return r;
}
__device__ __forceinline__ void mma_tf32(float* d,
                                         uint32_t a0, uint32_t a1, uint32_t a2, uint32_t a3,
                                         uint32_t b0, uint32_t b1) {
    asm("mma.sync.aligned.m16n8k8.row.col.f32.tf32.tf32.f32 "
        "{%0,%1,%2,%3}, {%4,%5,%6,%7}, {%8,%9}, {%0,%1,%2,%3};"
        : "+f"(d[0]), "+f"(d[1]), "+f"(d[2]), "+f"(d[3])
        : "r"(a0), "r"(a1), "r"(a2), "r"(a3), "r"(b0), "r"(b1));
}

// ---------------- scratch ----------------
__device__ float g_q [B_ * N_ * INNER_];
__device__ float g_pos[B_ * G_ * M_];
__device__ float g_k [B_ * M_ * INNER_];
__device__ float g_v [B_ * M_ * INNER_];
__device__ float g_ao[B_ * N_ * INNER_];

// ---------------- K1: q = grouped conv1x1, GEMM-tiled per group ----------------
__global__ __launch_bounds__(256) void k_qproj(const float* __restrict__ x,
                                               const float* __restrict__ px,
                                               const float* __restrict__ wq) {
    __shared__ float sIn[64][68];
    __shared__ float sW [64][68];
    int tok0 = blockIdx.x * 64;
    int g    = blockIdx.y;
    int tid  = threadIdx.x;
    int ty = tid >> 4, tx = tid & 15;

    const float* src = (g < 4) ? px : x;
    int cb = (g & 3) * 64;

#pragma unroll
    for (int it = 0; it < 4; it++) {
        int idx = tid + it * 256;
        int r = idx >> 4, c4 = (idx & 15) * 4;
        *(float4*)&sIn[r][c4] = *(const float4*)&src[(size_t)(tok0 + r) * D_ + cb + c4];
        *(float4*)&sW [r][c4] = *(const float4*)&wq [(size_t)(g * 64 + r) * 64 + c4];
    }
    __syncthreads();

    float acc[4][4];
#pragma unroll
    for (int i = 0; i < 4; i++)
#pragma unroll
        for (int j = 0; j < 4; j++) acc[i][j] = 0.f;

#pragma unroll
    for (int d0 = 0; d0 < 64; d0 += 4) {
        float4 av[4], wv[4];
#pragma unroll
        for (int i = 0; i < 4; i++) av[i] = *(const float4*)&sIn[ty + 16 * i][d0];
#pragma unroll
        for (int j = 0; j < 4; j++) wv[j] = *(const float4*)&sW[tx + 16 * j][d0];
#pragma unroll
        for (int i = 0; i < 4; i++)
#pragma unroll
            for (int j = 0; j < 4; j++) {
                acc[i][j] = fmaf(av[i].x, wv[j].x, acc[i][j]);
                acc[i][j] = fmaf(av[i].y, wv[j].y, acc[i][j]);
                acc[i][j] = fmaf(av[i].z, wv[j].z, acc[i][j]);
                acc[i][j] = fmaf(av[i].w, wv[j].w, acc[i][j]);
            }
    }
#pragma unroll
    for (int i = 0; i < 4; i++)
#pragma unroll
        for (int j = 0; j < 4; j++)
            g_q[(size_t)(tok0 + ty + 16 * i) * INNER_ + g * 64 + tx + 16 * j] = acc[i][j];
}

// ---------------- K2: offsets -> sampling positions ----------------
__global__ __launch_bounds__(256) void k_offsets(const float* __restrict__ w1,
                                                 const float* __restrict__ b1,
                                                 const float* __restrict__ w2) {
    __shared__ float red[8];
    int tid = threadIdx.x;
    int p = blockIdx.x * 4 + (tid >> 6);
    int c = tid & 63;
    int bc = p >> 10, m = p & (M_ - 1);
    int b = bc >> 3, g = bc & 7;
    const float* qbase = g_q + (size_t)b * N_ * INNER_ + g * 64 + c;

    float h = b1[c];
    int n0 = 4 * m - 1;
#pragma unroll
    for (int k = 0; k < KS_; k++) {
        int n = n0 + k;
        if (n >= 0 && n < N_) h = fmaf(qbase[(size_t)n * INNER_], w1[c * KS_ + k], h);
    }
    float ge  = 0.5f * h * (1.f + erff(h * 0.70710678118654752f));
    float val = ge * w2[c];
#pragma unroll
    for (int o = 16; o > 0; o >>= 1) val += __shfl_xor_sync(0xffffffffu, val, o);
    if ((tid & 31) == 0) red[tid >> 5] = val;
    __syncthreads();
    if (tid < 4) {
        float off = tanhf(red[2 * tid] + red[2 * tid + 1]) * 4.0f;
        int pp = blockIdx.x * 4 + tid;
        int mm = pp & (M_ - 1);
        g_pos[pp] = ((float)mm + off) * ((float)N_ / (float)(M_ - 1)) - 0.5f;
    }
}

// ---------------- K3: bilinear gather + k/v grouped conv1x1 ----------------
__global__ __launch_bounds__(128) void k_kv(const float* __restrict__ px,
                                            const float* __restrict__ wk,
                                            const float* __restrict__ wv) {
    int blk = blockIdx.x;
    int m = blk & (M_ - 1);
    int bc = blk >> 10;
    int b = bc >> 3, g = bc & 7;
    __shared__ float skv[32];
    int tid = threadIdx.x;
    if (tid < 32) {
        float pos = g_pos[blk];
        float fp  = floorf(pos);
        int   i0  = (int)fp;
        float w1f = pos - fp;
        const float* base = px + (size_t)b * N_ * D_ + g * 32 + tid;
        float v0 = (i0 >= 0     && i0     < N_) ? base[(size_t)i0 * D_]       : 0.f;
        float v1 = (i0 + 1 >= 0 && i0 + 1 < N_) ? base[(size_t)(i0 + 1) * D_] : 0.f;
        skv[tid] = v0 * (1.f - w1f) + v1 * w1f;
    }
    __syncthreads();
    int o = tid & 63;
    const float* w = (tid < 64 ? wk : wv) + (size_t)(g * 64 + o) * 32;
    float acc = 0.f;
#pragma unroll
    for (int d = 0; d < 32; d++) acc = fmaf(skv[d], w[d], acc);
    float* dst = (tid < 64 ? g_k : g_v);
    dst[((size_t)b * M_ + m) * INNER_ + g * 64 + o] = acc;
}

// ---------------- K4: flash attention, tf32 mma.sync, BQ=128, BK=64 ----------------
// smem: Q[128][68] | K/P alias [128][68] | V[64][72]
#define ATTN_SMEM ((128 * 68 + 128 * 68 + 64 * 72) * 4)
__global__ void __launch_bounds__(256, 2) k_attn() {
    int blk = blockIdx.x;            // b*256 + h*32 + qt
    int qt = blk & 31;
    int h  = (blk >> 5) & 7;
    int b  = blk >> 8;
    int n0 = qt << 7;

    extern __shared__ float smem[];
    float (*sQ)[68] = (float(*)[68])(smem);
    float (*sK)[68] = (float(*)[68])(smem + 128 * 68);   // rows 0..63 = K tile
    float (*sP)[68] = sK;                                 // rows 0..127 = P (after QK)
    float (*sV)[72] = (float(*)[72])(smem + 256 * 68);

    int tid  = threadIdx.x;
    int wid  = tid >> 5, lane = tid & 31;
    int r    = lane >> 2, t = lane & 3;
    int qb   = wid * 16;

    // ---- load Q (scaled, tf32) ----
    const float* qsrc = g_q + ((size_t)b * N_ + n0) * INNER_ + h * 64;
#pragma unroll
    for (int it = 0; it < 8; it++) {
        int idx = tid + it * 256;
        int rr = idx >> 4, c4 = (idx & 15) * 4;
        float4 qv = *(const float4*)&qsrc[(size_t)rr * INNER_ + c4];
        sQ[rr][c4 + 0] = __uint_as_float(f2tf32(qv.x * 0.125f));
        sQ[rr][c4 + 1] = __uint_as_float(f2tf32(qv.y * 0.125f));
        sQ[rr][c4 + 2] = __uint_as_float(f2tf32(qv.z * 0.125f));
        sQ[rr][c4 + 3] = __uint_as_float(f2tf32(qv.w * 0.125f));
    }

    float out[8][4];
#pragma unroll
    for (int nt = 0; nt < 8; nt++)
#pragma unroll
        for (int c = 0; c < 4; c++) out[nt][c] = 0.f;
    float rmax0 = -1e30f, rmax1 = -1e30f, rsum0 = 0.f, rsum1 = 0.f;

    const float* kbase = g_k + ((size_t)b * M_) * INNER_ + h * 64;
    const float* vbase = g_v + ((size_t)b * M_) * INNER_ + h * 64;
    __syncthreads();

    for (int kt = 0; kt < 16; kt++) {
        int m0 = kt << 6;
        // ---- load K, V tiles (tf32) ----
#pragma unroll
        for (int it = 0; it < 4; it++) {
            int idx = tid + it * 256;
            int rr = idx >> 4, c4 = (idx & 15) * 4;
            float4 k4 = *(const float4*)&kbase[(size_t)(m0 + rr) * INNER_ + c4];
            sK[rr][c4 + 0] = __uint_as_float(f2tf32(k4.x));
            sK[rr][c4 + 1] = __uint_as_float(f2tf32(k4.y));
            sK[rr][c4 + 2] = __uint_as_float(f2tf32(k4.z));
            sK[rr][c4 + 3] = __uint_as_float(f2tf32(k4.w));
            float4 v4 = *(const float4*)&vbase[(size_t)(m0 + rr) * INNER_ + c4];
            sV[rr][c4 + 0] = __uint_as_float(f2tf32(v4.x));
            sV[rr][c4 + 1] = __uint_as_float(f2tf32(v4.y));
            sV[rr][c4 + 2] = __uint_as_float(f2tf32(v4.z));
            sV[rr][c4 + 3] = __uint_as_float(f2tf32(v4.w));
        }
        __syncthreads();

        // ---- QK^T : S[16 x 64] per warp ----
        float s[8][4];
#pragma unroll
        for (int nt = 0; nt < 8; nt++)
#pragma unroll
            for (int c = 0; c < 4; c++) s[nt][c] = 0.f;

#pragma unroll
        for (int ks = 0; ks < 8; ks++) {
            int k0 = ks * 8;
            uint32_t a0 = __float_as_uint(sQ[qb + r    ][k0 + t    ]);
            uint32_t a1 = __float_as_uint(sQ[qb + r + 8][k0 + t    ]);
            uint32_t a2 = __float_as_uint(sQ[qb + r    ][k0 + t + 4]);
            uint32_t a3 = __float_as_uint(sQ[qb + r + 8][k0 + t + 4]);
#pragma unroll
            for (int nt = 0; nt < 8; nt++) {
                uint32_t b0 = __float_as_uint(sK[nt * 8 + r][k0 + t    ]);
                uint32_t b1 = __float_as_uint(sK[nt * 8 + r][k0 + t + 4]);
                mma_tf32(s[nt], a0, a1, a2, a3, b0, b1);
            }
        }
        __syncthreads();   // all warps done reading sK before P overwrites it

        // ---- online softmax (rows qb+r, qb+r+8) ----
        float lm0 = -1e30f, lm1 = -1e30f;
#pragma unroll
        for (int nt = 0; nt < 8; nt++) {
            lm0 = fmaxf(lm0, fmaxf(s[nt][0], s[nt][1]));
            lm1 = fmaxf(lm1, fmaxf(s[nt][2], s[nt][3]));
        }
        lm0 = fmaxf(lm0, __shfl_xor_sync(0xffffffffu, lm0, 1));
        lm0 = fmaxf(lm0, __shfl_xor_sync(0xffffffffu, lm0, 2));
        lm1 = fmaxf(lm1, __shfl_xor_sync(0xffffffffu, lm1, 1));
        lm1 = fmaxf(lm1, __shfl_xor_sync(0xffffffffu, lm1, 2));
        float nm0 = fmaxf(rmax0, lm0), nm1 = fmaxf(rmax1, lm1);
        float f0 = __expf(rmax0 - nm0), f1 = __expf(rmax1 - nm1);
        rmax0 = nm0; rmax1 = nm1;
        float ls0 = 0.f, ls1 = 0.f;
#pragma unroll
        for (int nt = 0; nt < 8; nt++) {
            float p00 = __expf(s[nt][0] - nm0);
            float p01 = __expf(s[nt][1] - nm0);
            float p10 = __expf(s[nt][2] - nm1);
            float p11 = __expf(s[nt][3] - nm1);
            ls0 += p00 + p01; ls1 += p10 + p11;
            int col = nt * 8 + 2 * t;
            sP[qb + r    ][col]     = __uint_as_float(f2tf32(p00));
            sP[qb + r    ][col + 1] = __uint_as_float(f2tf32(p01));
            sP[qb + r + 8][col]     = __uint_as_float(f2tf32(p10));
            sP[qb + r + 8][col + 1] = __uint_as_float(f2tf32(p11));
        }
        ls0 += __shfl_xor_sync(0xffffffffu, ls0, 1);
        ls0 += __shfl_xor_sync(0xffffffffu, ls0, 2);
        ls1 += __shfl_xor_sync(0xffffffffu, ls1, 1);
        ls1 += __shfl_xor_sync(0xffffffffu, ls1, 2);
        rsum0 = rsum0 * f0 + ls0;
        rsum1 = rsum1 * f1 + ls1;
#pragma unroll
        for (int nt = 0; nt < 8; nt++) {
            out[nt][0] *= f0; out[nt][1] *= f0;
            out[nt][2] *= f1; out[nt][3] *= f1;
        }
        __syncwarp();      // own P rows written before own A-frag reads

        // ---- P @ V ----
#pragma unroll
        for (int ks = 0; ks < 8; ks++) {
            int k0 = ks * 8;
            uint32_t a0 = __float_as_uint(sP[qb + r    ][k0 + t    ]);
            uint32_t a1 = __float_as_uint(sP[qb + r + 8][k0 + t    ]);
            uint32_t a2 = __float_as_uint(sP[qb + r    ][k0 + t + 4]);
            uint32_t a3 = __float_as_uint(sP[qb + r + 8][k0 + t + 4]);
#pragma unroll
            for (int nt = 0; nt < 8; nt++) {
                uint32_t b0 = __float_as_uint(sV[k0 + t    ][nt * 8 + r]);
                uint32_t b1 = __float_as_uint(sV[k0 + t + 4][nt * 8 + r]);
                mma_tf32(out[nt], a0, a1, a2, a3, b0, b1);
            }
        }
        __syncthreads();   // done reading sV / sP before next tile load
    }

    // ---- epilogue ----
    float inv0 = 1.f / rsum0, inv1 = 1.f / rsum1;
    float* dst = g_ao + ((size_t)b * N_ + n0) * INNER_ + h * 64;
#pragma unroll
    for (int nt = 0; nt < 8; nt++) {
        int col = nt * 8 + 2 * t;
        *(float2*)&dst[(size_t)(qb + r    ) * INNER_ + col] =
            make_float2(out[nt][0] * inv0, out[nt][1] * inv0);
        *(float2*)&dst[(size_t)(qb + r + 8) * INNER_ + col] =
            make_float2(out[nt][2] * inv1, out[nt][3] * inv1);
    }
}

// ---------------- K5: output projection 16384x256x512, 8x4 tiles, FFMA2 ----------------
#define OPROJ_SMEM ((128 + 64) * 68 * 4)
__global__ __launch_bounds__(256) void k_oproj(const float* __restrict__ wo,
                                               const float* __restrict__ bo,
                                               float* __restrict__ out) {
    extern __shared__ float smem[];
    float (*sA)[68] = (float(*)[68])(smem);
    float (*sW)[68] = (float(*)[68])(smem + 128 * 68);
    int row0 = blockIdx.x * 128;
    int o0   = blockIdx.y * 64;
    int tid  = threadIdx.x;
    int ty = tid >> 4, tx = tid & 15;

    unsigned long long c2[8][4];
#pragma unroll
    for (int i = 0; i < 8; i++)
#pragma unroll
        for (int j = 0; j < 4; j++) c2[i][j] = 0ull;

    for (int c0 = 0; c0 < INNER_; c0 += 64) {
#pragma unroll
        for (int it = 0; it < 8; it++) {
            int idx = tid + it * 256;
            int r = idx >> 4, c4 = (idx & 15) * 4;
            *(float4*)&sA[r][c4] = *(const float4*)&g_ao[(size_t)(row0 + r) * INNER_ + c0 + c4];
        }
#pragma unroll
        for (int it = 0; it < 4; it++) {
            int idx = tid + it * 256;
            int r = idx >> 4, c4 = (idx & 15) * 4;
            *(float4*)&sW[r][c4] = *(const float4*)&wo[(size_t)(o0 + r) * INNER_ + c0 + c4];
        }
        __syncthreads();
#pragma unroll 4
        for (int d0 = 0; d0 < 64; d0 += 4) {
            ulonglong2 a2[8], w2[4];
#pragma unroll
            for (int i = 0; i < 8; i++) a2[i] = *(const ulonglong2*)&sA[ty + 16 * i][d0];
#pragma unroll
            for (int j = 0; j < 4; j++) w2[j] = *(const ulonglong2*)&sW[tx + 16 * j][d0];
#pragma unroll
            for (int i = 0; i < 8; i++)
#pragma unroll
                for (int j = 0; j < 4; j++) {
                    ffma2(c2[i][j], a2[i].x, w2[j].x);
                    ffma2(c2[i][j], a2[i].y, w2[j].y);
                }
        }
        __syncthreads();
    }
#pragma unroll
    for (int i = 0; i < 8; i++)
#pragma unroll
        for (int j = 0; j < 4; j++) {
            float lo, hi; upk2(lo, hi, c2[i][j]);
            int o = o0 + tx + 16 * j;
            out[(size_t)(row0 + ty + 16 * i) * D_ + o] = lo + hi + bo[o];
        }
}

// ---------------- launch ----------------
extern "C" void kernel_launch(void* const* d_in, const int* in_sizes, int n_in,
                              void* d_out, int out_size) {
    const float* x      = (const float*)d_in[0];
    const float* prev_x = (const float*)d_in[1];
    const float* wq     = (const float*)d_in[2];
    const float* wk     = (const float*)d_in[3];
    const float* wv     = (const float*)d_in[4];
    const float* wo     = (const float*)d_in[5];
    const float* bo     = (const float*)d_in[6];
    const float* w_off1 = (const float*)d_in[7];
    const float* b_off1 = (const float*)d_in[8];
    const float* w_off2 = (const float*)d_in[9];
    float* out = (float*)d_out;

    cudaFuncSetAttribute(k_attn,  cudaFuncAttributeMaxDynamicSharedMemorySize, ATTN_SMEM);
    cudaFuncSetAttribute(k_oproj, cudaFuncAttributeMaxDynamicSharedMemorySize, OPROJ_SMEM);

    k_qproj  <<<dim3(B_ * N_ / 64, G_), 256>>>(x, prev_x, wq);
    k_offsets<<<(B_ * G_ * M_) / 4, 256>>>(w_off1, b_off1, w_off2);
    k_kv     <<<B_ * G_ * M_, 128>>>(prev_x, wk, wv);
    k_attn   <<<B_ * H_ * (N_ / 128), 256, ATTN_SMEM>>>();
    k_oproj  <<<dim3((B_ * N_) / 128, D_ / 64), 256, OPROJ_SMEM>>>(wo, bo, out);
}

// round 7
// speedup vs baseline: 9.9432x; 2.2538x over previous
#include <cuda_runtime.h>
#include <math.h>
#include <stdint.h>

// ---------------- constants (problem shapes are fixed) ----------------
#define B_   4
#define N_   4096
#define D_   256
#define H_   8
#define G_   8
#define DH_  64
#define INNER_ 512
#define M_   1024
#define KS_  6

// ---------------- tf32 mma helpers ----------------
__device__ __forceinline__ uint32_t f2tf32(float f) {
    uint32_t r; asm("cvt.rna.tf32.f32 %0, %1;" : "=r"(r) : "f"(f)); return r;
}
__device__ __forceinline__ void mma_tf32(float* d,
                                         uint32_t a0, uint32_t a1, uint32_t a2, uint32_t a3,
                                         uint32_t b0, uint32_t b1) {
    asm("mma.sync.aligned.m16n8k8.row.col.f32.tf32.tf32.f32 "
        "{%0,%1,%2,%3}, {%4,%5,%6,%7}, {%8,%9}, {%0,%1,%2,%3};"
        : "+f"(d[0]), "+f"(d[1]), "+f"(d[2]), "+f"(d[3])
        : "r"(a0), "r"(a1), "r"(a2), "r"(a3), "r"(b0), "r"(b1));
}

// ---------------- scratch ----------------
__device__ float g_q [B_ * N_ * INNER_];
__device__ float g_pos[B_ * G_ * M_];
__device__ float g_k [B_ * M_ * INNER_];
__device__ float g_v [B_ * M_ * INNER_];
__device__ float g_ao[B_ * N_ * INNER_];

// ---------------- K1: q = grouped conv1x1, GEMM-tiled per group ----------------
__global__ __launch_bounds__(256) void k_qproj(const float* __restrict__ x,
                                               const float* __restrict__ px,
                                               const float* __restrict__ wq) {
    __shared__ float sIn[64][68];
    __shared__ float sW [64][68];
    int tok0 = blockIdx.x * 64;
    int g    = blockIdx.y;
    int tid  = threadIdx.x;
    int ty = tid >> 4, tx = tid & 15;

    const float* src = (g < 4) ? px : x;
    int cb = (g & 3) * 64;

#pragma unroll
    for (int it = 0; it < 4; it++) {
        int idx = tid + it * 256;
        int r = idx >> 4, c4 = (idx & 15) * 4;
        *(float4*)&sIn[r][c4] = *(const float4*)&src[(size_t)(tok0 + r) * D_ + cb + c4];
        *(float4*)&sW [r][c4] = *(const float4*)&wq [(size_t)(g * 64 + r) * 64 + c4];
    }
    __syncthreads();

    float acc[4][4];
#pragma unroll
    for (int i = 0; i < 4; i++)
#pragma unroll
        for (int j = 0; j < 4; j++) acc[i][j] = 0.f;

#pragma unroll
    for (int d0 = 0; d0 < 64; d0 += 4) {
        float4 av[4], wv[4];
#pragma unroll
        for (int i = 0; i < 4; i++) av[i] = *(const float4*)&sIn[ty + 16 * i][d0];
#pragma unroll
        for (int j = 0; j < 4; j++) wv[j] = *(const float4*)&sW[tx + 16 * j][d0];
#pragma unroll
        for (int i = 0; i < 4; i++)
#pragma unroll
            for (int j = 0; j < 4; j++) {
                acc[i][j] = fmaf(av[i].x, wv[j].x, acc[i][j]);
                acc[i][j] = fmaf(av[i].y, wv[j].y, acc[i][j]);
                acc[i][j] = fmaf(av[i].z, wv[j].z, acc[i][j]);
                acc[i][j] = fmaf(av[i].w, wv[j].w, acc[i][j]);
            }
    }
#pragma unroll
    for (int i = 0; i < 4; i++)
#pragma unroll
        for (int j = 0; j < 4; j++)
            g_q[(size_t)(tok0 + ty + 16 * i) * INNER_ + g * 64 + tx + 16 * j] = acc[i][j];
}

// ---------------- K2: offsets -> sampling positions ----------------
__global__ __launch_bounds__(256) void k_offsets(const float* __restrict__ w1,
                                                 const float* __restrict__ b1,
                                                 const float* __restrict__ w2) {
    __shared__ float red[8];
    int tid = threadIdx.x;
    int p = blockIdx.x * 4 + (tid >> 6);
    int c = tid & 63;
    int bc = p >> 10, m = p & (M_ - 1);
    int b = bc >> 3, g = bc & 7;
    const float* qbase = g_q + (size_t)b * N_ * INNER_ + g * 64 + c;

    float h = b1[c];
    int n0 = 4 * m - 1;
#pragma unroll
    for (int k = 0; k < KS_; k++) {
        int n = n0 + k;
        if (n >= 0 && n < N_) h = fmaf(qbase[(size_t)n * INNER_], w1[c * KS_ + k], h);
    }
    float ge  = 0.5f * h * (1.f + erff(h * 0.70710678118654752f));
    float val = ge * w2[c];
#pragma unroll
    for (int o = 16; o > 0; o >>= 1) val += __shfl_xor_sync(0xffffffffu, val, o);
    if ((tid & 31) == 0) red[tid >> 5] = val;
    __syncthreads();
    if (tid < 4) {
        float off = tanhf(red[2 * tid] + red[2 * tid + 1]) * 4.0f;
        int pp = blockIdx.x * 4 + tid;
        int mm = pp & (M_ - 1);
        g_pos[pp] = ((float)mm + off) * ((float)N_ / (float)(M_ - 1)) - 0.5f;
    }
}

// ---------------- K3: bilinear gather + k/v conv1x1, 8 m per block ----------------
__global__ __launch_bounds__(256) void k_kv(const float* __restrict__ px,
                                            const float* __restrict__ wk,
                                            const float* __restrict__ wv) {
    __shared__ float skv[8][33];
    __shared__ float sW [128][33];      // rows 0..63 = wk rows, 64..127 = wv rows
    int blk = blockIdx.x;               // 4096 blocks
    int bc  = blk >> 7;                 // (b,g) index
    int m0  = (blk & 127) * 8;
    int b = bc >> 3, g = bc & 7;
    int tid = threadIdx.x;

    // stage group weights (coalesced)
#pragma unroll
    for (int it = 0; it < 16; it++) {
        int idx = tid + it * 256;       // 4096 words
        int row = idx >> 5, d = idx & 31;
        const float* w = (row < 64) ? wk : wv;
        sW[row][d] = w[(size_t)(g * 64 + (row & 63)) * 32 + d];
    }

    // gather: one (msub, ch) per thread
    {
        int msub = tid >> 5, ch = tid & 31;
        float pos = g_pos[bc * M_ + m0 + msub];
        float fp  = floorf(pos);
        int   i0  = (int)fp;
        float w1f = pos - fp;
        const float* base = px + (size_t)b * N_ * D_ + g * 32 + ch;
        float v0 = (i0 >= 0     && i0     < N_) ? base[(size_t)i0 * D_]       : 0.f;
        float v1 = (i0 + 1 >= 0 && i0 + 1 < N_) ? base[(size_t)(i0 + 1) * D_] : 0.f;
        skv[msub][ch] = v0 * (1.f - w1f) + v1 * w1f;
    }
    __syncthreads();

    // compute: 1024 outputs (8 m x {k,v} x 64 o), 4 per thread
#pragma unroll
    for (int u = 0; u < 4; u++) {
        int idx  = tid + u * 256;
        int msub = idx >> 7, rem = idx & 127;
        int kv   = rem >> 6, o = rem & 63;
        float acc = 0.f;
#pragma unroll
        for (int d = 0; d < 32; d++)
            acc = fmaf(skv[msub][d], sW[kv * 64 + o][d], acc);
        float* dst = kv ? g_v : g_k;
        dst[((size_t)b * M_ + m0 + msub) * INNER_ + g * 64 + o] = acc;
    }
}

// ---------------- K4: flash attention, tf32 mma.sync, BQ=128, BK=64 ----------------
// smem: Q[128][68] | K/P alias [128][68] | V[64][72]
#define ATTN_SMEM ((128 * 68 + 128 * 68 + 64 * 72) * 4)
__global__ void __launch_bounds__(256, 2) k_attn() {
    int blk = blockIdx.x;            // b*256 + h*32 + qt
    int qt = blk & 31;
    int h  = (blk >> 5) & 7;
    int b  = blk >> 8;
    int n0 = qt << 7;

    extern __shared__ float smem[];
    float (*sQ)[68] = (float(*)[68])(smem);
    float (*sK)[68] = (float(*)[68])(smem + 128 * 68);
    float (*sP)[68] = sK;
    float (*sV)[72] = (float(*)[72])(smem + 256 * 68);

    int tid  = threadIdx.x;
    int wid  = tid >> 5, lane = tid & 31;
    int r    = lane >> 2, t = lane & 3;
    int qb   = wid * 16;

    const float* qsrc = g_q + ((size_t)b * N_ + n0) * INNER_ + h * 64;
#pragma unroll
    for (int it = 0; it < 8; it++) {
        int idx = tid + it * 256;
        int rr = idx >> 4, c4 = (idx & 15) * 4;
        float4 qv = *(const float4*)&qsrc[(size_t)rr * INNER_ + c4];
        sQ[rr][c4 + 0] = __uint_as_float(f2tf32(qv.x * 0.125f));
        sQ[rr][c4 + 1] = __uint_as_float(f2tf32(qv.y * 0.125f));
        sQ[rr][c4 + 2] = __uint_as_float(f2tf32(qv.z * 0.125f));
        sQ[rr][c4 + 3] = __uint_as_float(f2tf32(qv.w * 0.125f));
    }

    float out[8][4];
#pragma unroll
    for (int nt = 0; nt < 8; nt++)
#pragma unroll
        for (int c = 0; c < 4; c++) out[nt][c] = 0.f;
    float rmax0 = -1e30f, rmax1 = -1e30f, rsum0 = 0.f, rsum1 = 0.f;

    const float* kbase = g_k + ((size_t)b * M_) * INNER_ + h * 64;
    const float* vbase = g_v + ((size_t)b * M_) * INNER_ + h * 64;
    __syncthreads();

    for (int kt = 0; kt < 16; kt++) {
        int m0 = kt << 6;
#pragma unroll
        for (int it = 0; it < 4; it++) {
            int idx = tid + it * 256;
            int rr = idx >> 4, c4 = (idx & 15) * 4;
            float4 k4 = *(const float4*)&kbase[(size_t)(m0 + rr) * INNER_ + c4];
            sK[rr][c4 + 0] = __uint_as_float(f2tf32(k4.x));
            sK[rr][c4 + 1] = __uint_as_float(f2tf32(k4.y));
            sK[rr][c4 + 2] = __uint_as_float(f2tf32(k4.z));
            sK[rr][c4 + 3] = __uint_as_float(f2tf32(k4.w));
            float4 v4 = *(const float4*)&vbase[(size_t)(m0 + rr) * INNER_ + c4];
            sV[rr][c4 + 0] = __uint_as_float(f2tf32(v4.x));
            sV[rr][c4 + 1] = __uint_as_float(f2tf32(v4.y));
            sV[rr][c4 + 2] = __uint_as_float(f2tf32(v4.z));
            sV[rr][c4 + 3] = __uint_as_float(f2tf32(v4.w));
        }
        __syncthreads();

        float s[8][4];
#pragma unroll
        for (int nt = 0; nt < 8; nt++)
#pragma unroll
            for (int c = 0; c < 4; c++) s[nt][c] = 0.f;

#pragma unroll
        for (int ks = 0; ks < 8; ks++) {
            int k0 = ks * 8;
            uint32_t a0 = __float_as_uint(sQ[qb + r    ][k0 + t    ]);
            uint32_t a1 = __float_as_uint(sQ[qb + r + 8][k0 + t    ]);
            uint32_t a2 = __float_as_uint(sQ[qb + r    ][k0 + t + 4]);
            uint32_t a3 = __float_as_uint(sQ[qb + r + 8][k0 + t + 4]);
#pragma unroll
            for (int nt = 0; nt < 8; nt++) {
                uint32_t b0 = __float_as_uint(sK[nt * 8 + r][k0 + t    ]);
                uint32_t b1 = __float_as_uint(sK[nt * 8 + r][k0 + t + 4]);
                mma_tf32(s[nt], a0, a1, a2, a3, b0, b1);
            }
        }
        __syncthreads();

        float lm0 = -1e30f, lm1 = -1e30f;
#pragma unroll
        for (int nt = 0; nt < 8; nt++) {
            lm0 = fmaxf(lm0, fmaxf(s[nt][0], s[nt][1]));
            lm1 = fmaxf(lm1, fmaxf(s[nt][2], s[nt][3]));
        }
        lm0 = fmaxf(lm0, __shfl_xor_sync(0xffffffffu, lm0, 1));
        lm0 = fmaxf(lm0, __shfl_xor_sync(0xffffffffu, lm0, 2));
        lm1 = fmaxf(lm1, __shfl_xor_sync(0xffffffffu, lm1, 1));
        lm1 = fmaxf(lm1, __shfl_xor_sync(0xffffffffu, lm1, 2));
        float nm0 = fmaxf(rmax0, lm0), nm1 = fmaxf(rmax1, lm1);
        float f0 = __expf(rmax0 - nm0), f1 = __expf(rmax1 - nm1);
        rmax0 = nm0; rmax1 = nm1;
        float ls0 = 0.f, ls1 = 0.f;
#pragma unroll
        for (int nt = 0; nt < 8; nt++) {
            float p00 = __expf(s[nt][0] - nm0);
            float p01 = __expf(s[nt][1] - nm0);
            float p10 = __expf(s[nt][2] - nm1);
            float p11 = __expf(s[nt][3] - nm1);
            ls0 += p00 + p01; ls1 += p10 + p11;
            int col = nt * 8 + 2 * t;
            sP[qb + r    ][col]     = __uint_as_float(f2tf32(p00));
            sP[qb + r    ][col + 1] = __uint_as_float(f2tf32(p01));
            sP[qb + r + 8][col]     = __uint_as_float(f2tf32(p10));
            sP[qb + r + 8][col + 1] = __uint_as_float(f2tf32(p11));
        }
        ls0 += __shfl_xor_sync(0xffffffffu, ls0, 1);
        ls0 += __shfl_xor_sync(0xffffffffu, ls0, 2);
        ls1 += __shfl_xor_sync(0xffffffffu, ls1, 1);
        ls1 += __shfl_xor_sync(0xffffffffu, ls1, 2);
        rsum0 = rsum0 * f0 + ls0;
        rsum1 = rsum1 * f1 + ls1;
#pragma unroll
        for (int nt = 0; nt < 8; nt++) {
            out[nt][0] *= f0; out[nt][1] *= f0;
            out[nt][2] *= f1; out[nt][3] *= f1;
        }
        __syncwarp();

#pragma unroll
        for (int ks = 0; ks < 8; ks++) {
            int k0 = ks * 8;
            uint32_t a0 = __float_as_uint(sP[qb + r    ][k0 + t    ]);
            uint32_t a1 = __float_as_uint(sP[qb + r + 8][k0 + t    ]);
            uint32_t a2 = __float_as_uint(sP[qb + r    ][k0 + t + 4]);
            uint32_t a3 = __float_as_uint(sP[qb + r + 8][k0 + t + 4]);
#pragma unroll
            for (int nt = 0; nt < 8; nt++) {
                uint32_t b0 = __float_as_uint(sV[k0 + t    ][nt * 8 + r]);
                uint32_t b1 = __float_as_uint(sV[k0 + t + 4][nt * 8 + r]);
                mma_tf32(out[nt], a0, a1, a2, a3, b0, b1);
            }
        }
        __syncthreads();
    }

    float inv0 = 1.f / rsum0, inv1 = 1.f / rsum1;
    float* dst = g_ao + ((size_t)b * N_ + n0) * INNER_ + h * 64;
#pragma unroll
    for (int nt = 0; nt < 8; nt++) {
        int col = nt * 8 + 2 * t;
        *(float2*)&dst[(size_t)(qb + r    ) * INNER_ + col] =
            make_float2(out[nt][0] * inv0, out[nt][1] * inv0);
        *(float2*)&dst[(size_t)(qb + r + 8) * INNER_ + col] =
            make_float2(out[nt][2] * inv1, out[nt][3] * inv1);
    }
}

// ---------------- K5: output projection, tf32 mma, 128x64 blocks ----------------
// smem: A[128][68] | W[64][68]
#define OPROJ_SMEM ((128 * 68 + 64 * 68) * 4)
__global__ void __launch_bounds__(256, 2) k_oproj(const float* __restrict__ wo,
                                                  const float* __restrict__ bo,
                                                  float* __restrict__ out) {
    extern __shared__ float smem[];
    float (*sA)[68] = (float(*)[68])(smem);
    float (*sW)[68] = (float(*)[68])(smem + 128 * 68);
    int row0 = blockIdx.x * 128;
    int o0   = blockIdx.y * 64;
    int tid  = threadIdx.x;
    int wid  = tid >> 5, lane = tid & 31;
    int r    = lane >> 2, t = lane & 3;
    int qb   = wid * 16;

    float s[8][4];
#pragma unroll
    for (int nt = 0; nt < 8; nt++)
#pragma unroll
        for (int c = 0; c < 4; c++) s[nt][c] = 0.f;

    for (int c0 = 0; c0 < INNER_; c0 += 64) {
#pragma unroll
        for (int it = 0; it < 8; it++) {
            int idx = tid + it * 256;
            int rr = idx >> 4, c4 = (idx & 15) * 4;
            float4 a4 = *(const float4*)&g_ao[(size_t)(row0 + rr) * INNER_ + c0 + c4];
            sA[rr][c4 + 0] = __uint_as_float(f2tf32(a4.x));
            sA[rr][c4 + 1] = __uint_as_float(f2tf32(a4.y));
            sA[rr][c4 + 2] = __uint_as_float(f2tf32(a4.z));
            sA[rr][c4 + 3] = __uint_as_float(f2tf32(a4.w));
        }
#pragma unroll
        for (int it = 0; it < 4; it++) {
            int idx = tid + it * 256;
            int rr = idx >> 4, c4 = (idx & 15) * 4;
            float4 w4 = *(const float4*)&wo[(size_t)(o0 + rr) * INNER_ + c0 + c4];
            sW[rr][c4 + 0] = __uint_as_float(f2tf32(w4.x));
            sW[rr][c4 + 1] = __uint_as_float(f2tf32(w4.y));
            sW[rr][c4 + 2] = __uint_as_float(f2tf32(w4.z));
            sW[rr][c4 + 3] = __uint_as_float(f2tf32(w4.w));
        }
        __syncthreads();
#pragma unroll
        for (int ks = 0; ks < 8; ks++) {
            int k0 = ks * 8;
            uint32_t a0 = __float_as_uint(sA[qb + r    ][k0 + t    ]);
            uint32_t a1 = __float_as_uint(sA[qb + r + 8][k0 + t    ]);
            uint32_t a2 = __float_as_uint(sA[qb + r    ][k0 + t + 4]);
            uint32_t a3 = __float_as_uint(sA[qb + r + 8][k0 + t + 4]);
#pragma unroll
            for (int nt = 0; nt < 8; nt++) {
                uint32_t b0 = __float_as_uint(sW[nt * 8 + r][k0 + t    ]);
                uint32_t b1 = __float_as_uint(sW[nt * 8 + r][k0 + t + 4]);
                mma_tf32(s[nt], a0, a1, a2, a3, b0, b1);
            }
        }
        __syncthreads();
    }

#pragma unroll
    for (int nt = 0; nt < 8; nt++) {
        int col = nt * 8 + 2 * t;
        int o = o0 + col;
        float b0 = bo[o], b1 = bo[o + 1];
        *(float2*)&out[(size_t)(row0 + qb + r    ) * D_ + o] =
            make_float2(s[nt][0] + b0, s[nt][1] + b1);
        *(float2*)&out[(size_t)(row0 + qb + r + 8) * D_ + o] =
            make_float2(s[nt][2] + b0, s[nt][3] + b1);
    }
}

// ---------------- launch ----------------
extern "C" void kernel_launch(void* const* d_in, const int* in_sizes, int n_in,
                              void* d_out, int out_size) {
    const float* x      = (const float*)d_in[0];
    const float* prev_x = (const float*)d_in[1];
    const float* wq     = (const float*)d_in[2];
    const float* wk     = (const float*)d_in[3];
    const float* wv     = (const float*)d_in[4];
    const float* wo     = (const float*)d_in[5];
    const float* bo     = (const float*)d_in[6];
    const float* w_off1 = (const float*)d_in[7];
    const float* b_off1 = (const float*)d_in[8];
    const float* w_off2 = (const float*)d_in[9];
    float* out = (float*)d_out;

    cudaFuncSetAttribute(k_attn,  cudaFuncAttributeMaxDynamicSharedMemorySize, ATTN_SMEM);
    cudaFuncSetAttribute(k_oproj, cudaFuncAttributeMaxDynamicSharedMemorySize, OPROJ_SMEM);

    k_qproj  <<<dim3(B_ * N_ / 64, G_), 256>>>(x, prev_x, wq);
    k_offsets<<<(B_ * G_ * M_) / 4, 256>>>(w_off1, b_off1, w_off2);
    k_kv     <<<(B_ * G_ * M_) / 8, 256>>>(prev_x, wk, wv);
    k_attn   <<<B_ * H_ * (N_ / 128), 256, ATTN_SMEM>>>();
    k_oproj  <<<dim3((B_ * N_) / 128, D_ / 64), 256, OPROJ_SMEM>>>(wo, bo, out);
}

// round 8
// speedup vs baseline: 10.1706x; 1.0229x over previous
#include <cuda_runtime.h>
#include <math.h>
#include <stdint.h>

// ---------------- constants (problem shapes are fixed) ----------------
#define B_   4
#define N_   4096
#define D_   256
#define H_   8
#define G_   8
#define DH_  64
#define INNER_ 512
#define M_   1024
#define KS_  6

// ---------------- tf32 mma helpers ----------------
__device__ __forceinline__ uint32_t f2tf32(float f) {
    uint32_t r; asm("cvt.rna.tf32.f32 %0, %1;" : "=r"(r) : "f"(f)); return r;
}
__device__ __forceinline__ void mma_tf32(float* d,
                                         uint32_t a0, uint32_t a1, uint32_t a2, uint32_t a3,
                                         uint32_t b0, uint32_t b1) {
    asm("mma.sync.aligned.m16n8k8.row.col.f32.tf32.tf32.f32 "
        "{%0,%1,%2,%3}, {%4,%5,%6,%7}, {%8,%9}, {%0,%1,%2,%3};"
        : "+f"(d[0]), "+f"(d[1]), "+f"(d[2]), "+f"(d[3])
        : "r"(a0), "r"(a1), "r"(a2), "r"(a3), "r"(b0), "r"(b1));
}

// ---------------- scratch ----------------
__device__ float g_q [B_ * N_ * INNER_];
__device__ float g_pos[B_ * G_ * M_];
__device__ float g_k [B_ * M_ * INNER_];
__device__ float g_v [B_ * M_ * INNER_];
__device__ float g_ao[B_ * N_ * INNER_];

// ---------------- K1: q = grouped conv1x1, GEMM-tiled per group ----------------
__global__ __launch_bounds__(256) void k_qproj(const float* __restrict__ x,
                                               const float* __restrict__ px,
                                               const float* __restrict__ wq) {
    __shared__ float sIn[64][68];
    __shared__ float sW [64][68];
    int tok0 = blockIdx.x * 64;
    int g    = blockIdx.y;
    int tid  = threadIdx.x;
    int ty = tid >> 4, tx = tid & 15;

    const float* src = (g < 4) ? px : x;
    int cb = (g & 3) * 64;

#pragma unroll
    for (int it = 0; it < 4; it++) {
        int idx = tid + it * 256;
        int r = idx >> 4, c4 = (idx & 15) * 4;
        *(float4*)&sIn[r][c4] = *(const float4*)&src[(size_t)(tok0 + r) * D_ + cb + c4];
        *(float4*)&sW [r][c4] = *(const float4*)&wq [(size_t)(g * 64 + r) * 64 + c4];
    }
    __syncthreads();

    float acc[4][4];
#pragma unroll
    for (int i = 0; i < 4; i++)
#pragma unroll
        for (int j = 0; j < 4; j++) acc[i][j] = 0.f;

#pragma unroll
    for (int d0 = 0; d0 < 64; d0 += 4) {
        float4 av[4], wv[4];
#pragma unroll
        for (int i = 0; i < 4; i++) av[i] = *(const float4*)&sIn[ty + 16 * i][d0];
#pragma unroll
        for (int j = 0; j < 4; j++) wv[j] = *(const float4*)&sW[tx + 16 * j][d0];
#pragma unroll
        for (int i = 0; i < 4; i++)
#pragma unroll
            for (int j = 0; j < 4; j++) {
                acc[i][j] = fmaf(av[i].x, wv[j].x, acc[i][j]);
                acc[i][j] = fmaf(av[i].y, wv[j].y, acc[i][j]);
                acc[i][j] = fmaf(av[i].z, wv[j].z, acc[i][j]);
                acc[i][j] = fmaf(av[i].w, wv[j].w, acc[i][j]);
            }
    }
#pragma unroll
    for (int i = 0; i < 4; i++)
#pragma unroll
        for (int j = 0; j < 4; j++)
            g_q[(size_t)(tok0 + ty + 16 * i) * INNER_ + g * 64 + tx + 16 * j] = acc[i][j];
}

// ---------------- K2: offsets -> sampling positions ----------------
__global__ __launch_bounds__(256) void k_offsets(const float* __restrict__ w1,
                                                 const float* __restrict__ b1,
                                                 const float* __restrict__ w2) {
    __shared__ float red[8];
    int tid = threadIdx.x;
    int p = blockIdx.x * 4 + (tid >> 6);
    int c = tid & 63;
    int bc = p >> 10, m = p & (M_ - 1);
    int b = bc >> 3, g = bc & 7;
    const float* qbase = g_q + (size_t)b * N_ * INNER_ + g * 64 + c;

    float h = b1[c];
    int n0 = 4 * m - 1;
#pragma unroll
    for (int k = 0; k < KS_; k++) {
        int n = n0 + k;
        if (n >= 0 && n < N_) h = fmaf(qbase[(size_t)n * INNER_], w1[c * KS_ + k], h);
    }
    float ge  = 0.5f * h * (1.f + erff(h * 0.70710678118654752f));
    float val = ge * w2[c];
#pragma unroll
    for (int o = 16; o > 0; o >>= 1) val += __shfl_xor_sync(0xffffffffu, val, o);
    if ((tid & 31) == 0) red[tid >> 5] = val;
    __syncthreads();
    if (tid < 4) {
        float off = tanhf(red[2 * tid] + red[2 * tid + 1]) * 4.0f;
        int pp = blockIdx.x * 4 + tid;
        int mm = pp & (M_ - 1);
        g_pos[pp] = ((float)mm + off) * ((float)N_ / (float)(M_ - 1)) - 0.5f;
    }
}

// ---------------- K3: bilinear gather + k/v conv1x1, 8 m per block ----------------
__global__ __launch_bounds__(256) void k_kv(const float* __restrict__ px,
                                            const float* __restrict__ wk,
                                            const float* __restrict__ wv) {
    __shared__ float skv[8][33];
    __shared__ float sW [128][33];
    int blk = blockIdx.x;
    int bc  = blk >> 7;
    int m0  = (blk & 127) * 8;
    int b = bc >> 3, g = bc & 7;
    int tid = threadIdx.x;

#pragma unroll
    for (int it = 0; it < 16; it++) {
        int idx = tid + it * 256;
        int row = idx >> 5, d = idx & 31;
        const float* w = (row < 64) ? wk : wv;
        sW[row][d] = w[(size_t)(g * 64 + (row & 63)) * 32 + d];
    }

    {
        int msub = tid >> 5, ch = tid & 31;
        float pos = g_pos[bc * M_ + m0 + msub];
        float fp  = floorf(pos);
        int   i0  = (int)fp;
        float w1f = pos - fp;
        const float* base = px + (size_t)b * N_ * D_ + g * 32 + ch;
        float v0 = (i0 >= 0     && i0     < N_) ? base[(size_t)i0 * D_]       : 0.f;
        float v1 = (i0 + 1 >= 0 && i0 + 1 < N_) ? base[(size_t)(i0 + 1) * D_] : 0.f;
        skv[msub][ch] = v0 * (1.f - w1f) + v1 * w1f;
    }
    __syncthreads();

#pragma unroll
    for (int u = 0; u < 4; u++) {
        int idx  = tid + u * 256;
        int msub = idx >> 7, rem = idx & 127;
        int kv   = rem >> 6, o = rem & 63;
        float acc = 0.f;
#pragma unroll
        for (int d = 0; d < 32; d++)
            acc = fmaf(skv[msub][d], sW[kv * 64 + o][d], acc);
        float* dst = kv ? g_v : g_k;
        dst[((size_t)b * M_ + m0 + msub) * INNER_ + g * 64 + o] = acc;
    }
}

// ---------------- K4: flash attention, tf32 mma, 4 warps x 32 q-rows ----------------
// smem: Q[128][68] | K/P alias [128][68] | V[64][72]
#define ATTN_SMEM ((128 * 68 + 128 * 68 + 64 * 72) * 4)
__global__ void __launch_bounds__(128, 2) k_attn() {
    int blk = blockIdx.x;            // b*256 + h*32 + qt
    int qt = blk & 31;
    int h  = (blk >> 5) & 7;
    int b  = blk >> 8;
    int n0 = qt << 7;

    extern __shared__ float smem[];
    float (*sQ)[68] = (float(*)[68])(smem);
    float (*sK)[68] = (float(*)[68])(smem + 128 * 68);
    float (*sP)[68] = sK;
    float (*sV)[72] = (float(*)[72])(smem + 256 * 68);

    int tid  = threadIdx.x;
    int wid  = tid >> 5, lane = tid & 31;
    int r    = lane >> 2, t = lane & 3;
    int qb   = wid * 32;                 // 32 q rows per warp

    // ---- load Q (scaled, tf32) ----
    const float* qsrc = g_q + ((size_t)b * N_ + n0) * INNER_ + h * 64;
#pragma unroll
    for (int it = 0; it < 16; it++) {
        int idx = tid + it * 128;
        int rr = idx >> 4, c4 = (idx & 15) * 4;
        float4 qv = *(const float4*)&qsrc[(size_t)rr * INNER_ + c4];
        sQ[rr][c4 + 0] = __uint_as_float(f2tf32(qv.x * 0.125f));
        sQ[rr][c4 + 1] = __uint_as_float(f2tf32(qv.y * 0.125f));
        sQ[rr][c4 + 2] = __uint_as_float(f2tf32(qv.z * 0.125f));
        sQ[rr][c4 + 3] = __uint_as_float(f2tf32(qv.w * 0.125f));
    }

    float out[2][8][4];
#pragma unroll
    for (int u = 0; u < 2; u++)
#pragma unroll
        for (int nt = 0; nt < 8; nt++)
#pragma unroll
            for (int c = 0; c < 4; c++) out[u][nt][c] = 0.f;
    float rmax[2][2], rsum[2][2];
#pragma unroll
    for (int u = 0; u < 2; u++) { rmax[u][0] = rmax[u][1] = -1e30f; rsum[u][0] = rsum[u][1] = 0.f; }

    const float* kbase = g_k + ((size_t)b * M_) * INNER_ + h * 64;
    const float* vbase = g_v + ((size_t)b * M_) * INNER_ + h * 64;
    __syncthreads();

    for (int kt = 0; kt < 16; kt++) {
        int m0 = kt << 6;
        // ---- load K, V tiles (tf32) ----
#pragma unroll
        for (int it = 0; it < 8; it++) {
            int idx = tid + it * 128;
            int rr = idx >> 4, c4 = (idx & 15) * 4;
            float4 k4 = *(const float4*)&kbase[(size_t)(m0 + rr) * INNER_ + c4];
            sK[rr][c4 + 0] = __uint_as_float(f2tf32(k4.x));
            sK[rr][c4 + 1] = __uint_as_float(f2tf32(k4.y));
            sK[rr][c4 + 2] = __uint_as_float(f2tf32(k4.z));
            sK[rr][c4 + 3] = __uint_as_float(f2tf32(k4.w));
            float4 v4 = *(const float4*)&vbase[(size_t)(m0 + rr) * INNER_ + c4];
            sV[rr][c4 + 0] = __uint_as_float(f2tf32(v4.x));
            sV[rr][c4 + 1] = __uint_as_float(f2tf32(v4.y));
            sV[rr][c4 + 2] = __uint_as_float(f2tf32(v4.z));
            sV[rr][c4 + 3] = __uint_as_float(f2tf32(v4.w));
        }
        __syncthreads();

        // ---- QK^T : S[32 x 64] per warp (two 16-row tiles) ----
        float s[2][8][4];
#pragma unroll
        for (int u = 0; u < 2; u++)
#pragma unroll
            for (int nt = 0; nt < 8; nt++)
#pragma unroll
                for (int c = 0; c < 4; c++) s[u][nt][c] = 0.f;

#pragma unroll
        for (int ks = 0; ks < 8; ks++) {
            int k0 = ks * 8;
            uint32_t a[2][4];
#pragma unroll
            for (int u = 0; u < 2; u++) {
                int rb = qb + u * 16;
                a[u][0] = __float_as_uint(sQ[rb + r    ][k0 + t    ]);
                a[u][1] = __float_as_uint(sQ[rb + r + 8][k0 + t    ]);
                a[u][2] = __float_as_uint(sQ[rb + r    ][k0 + t + 4]);
                a[u][3] = __float_as_uint(sQ[rb + r + 8][k0 + t + 4]);
            }
#pragma unroll
            for (int nt = 0; nt < 8; nt++) {
                uint32_t b0 = __float_as_uint(sK[nt * 8 + r][k0 + t    ]);
                uint32_t b1 = __float_as_uint(sK[nt * 8 + r][k0 + t + 4]);
                mma_tf32(s[0][nt], a[0][0], a[0][1], a[0][2], a[0][3], b0, b1);
                mma_tf32(s[1][nt], a[1][0], a[1][1], a[1][2], a[1][3], b0, b1);
            }
        }
        __syncthreads();   // all warps done reading sK before P overwrites

        // ---- online softmax (two row-tiles) ----
#pragma unroll
        for (int u = 0; u < 2; u++) {
            int rb = qb + u * 16;
            float lm0 = -1e30f, lm1 = -1e30f;
#pragma unroll
            for (int nt = 0; nt < 8; nt++) {
                lm0 = fmaxf(lm0, fmaxf(s[u][nt][0], s[u][nt][1]));
                lm1 = fmaxf(lm1, fmaxf(s[u][nt][2], s[u][nt][3]));
            }
            lm0 = fmaxf(lm0, __shfl_xor_sync(0xffffffffu, lm0, 1));
            lm0 = fmaxf(lm0, __shfl_xor_sync(0xffffffffu, lm0, 2));
            lm1 = fmaxf(lm1, __shfl_xor_sync(0xffffffffu, lm1, 1));
            lm1 = fmaxf(lm1, __shfl_xor_sync(0xffffffffu, lm1, 2));
            float nm0 = fmaxf(rmax[u][0], lm0), nm1 = fmaxf(rmax[u][1], lm1);
            float f0 = __expf(rmax[u][0] - nm0), f1 = __expf(rmax[u][1] - nm1);
            rmax[u][0] = nm0; rmax[u][1] = nm1;
            float ls0 = 0.f, ls1 = 0.f;
#pragma unroll
            for (int nt = 0; nt < 8; nt++) {
                float p00 = __expf(s[u][nt][0] - nm0);
                float p01 = __expf(s[u][nt][1] - nm0);
                float p10 = __expf(s[u][nt][2] - nm1);
                float p11 = __expf(s[u][nt][3] - nm1);
                ls0 += p00 + p01; ls1 += p10 + p11;
                int col = nt * 8 + 2 * t;
                sP[rb + r    ][col]     = __uint_as_float(f2tf32(p00));
                sP[rb + r    ][col + 1] = __uint_as_float(f2tf32(p01));
                sP[rb + r + 8][col]     = __uint_as_float(f2tf32(p10));
                sP[rb + r + 8][col + 1] = __uint_as_float(f2tf32(p11));
            }
            ls0 += __shfl_xor_sync(0xffffffffu, ls0, 1);
            ls0 += __shfl_xor_sync(0xffffffffu, ls0, 2);
            ls1 += __shfl_xor_sync(0xffffffffu, ls1, 1);
            ls1 += __shfl_xor_sync(0xffffffffu, ls1, 2);
            rsum[u][0] = rsum[u][0] * f0 + ls0;
            rsum[u][1] = rsum[u][1] * f1 + ls1;
#pragma unroll
            for (int nt = 0; nt < 8; nt++) {
                out[u][nt][0] *= f0; out[u][nt][1] *= f0;
                out[u][nt][2] *= f1; out[u][nt][3] *= f1;
            }
        }
        __syncwarp();      // own P rows written before own A-frag reads

        // ---- P @ V ----
#pragma unroll
        for (int ks = 0; ks < 8; ks++) {
            int k0 = ks * 8;
            uint32_t a[2][4];
#pragma unroll
            for (int u = 0; u < 2; u++) {
                int rb = qb + u * 16;
                a[u][0] = __float_as_uint(sP[rb + r    ][k0 + t    ]);
                a[u][1] = __float_as_uint(sP[rb + r + 8][k0 + t    ]);
                a[u][2] = __float_as_uint(sP[rb + r    ][k0 + t + 4]);
                a[u][3] = __float_as_uint(sP[rb + r + 8][k0 + t + 4]);
            }
#pragma unroll
            for (int nt = 0; nt < 8; nt++) {
                uint32_t b0 = __float_as_uint(sV[k0 + t    ][nt * 8 + r]);
                uint32_t b1 = __float_as_uint(sV[k0 + t + 4][nt * 8 + r]);
                mma_tf32(out[0][nt], a[0][0], a[0][1], a[0][2], a[0][3], b0, b1);
                mma_tf32(out[1][nt], a[1][0], a[1][1], a[1][2], a[1][3], b0, b1);
            }
        }
        __syncthreads();   // done reading sV/sP before next tile load
    }

    // ---- epilogue ----
    float* dst = g_ao + ((size_t)b * N_ + n0) * INNER_ + h * 64;
#pragma unroll
    for (int u = 0; u < 2; u++) {
        int rb = qb + u * 16;
        float inv0 = 1.f / rsum[u][0], inv1 = 1.f / rsum[u][1];
#pragma unroll
        for (int nt = 0; nt < 8; nt++) {
            int col = nt * 8 + 2 * t;
            *(float2*)&dst[(size_t)(rb + r    ) * INNER_ + col] =
                make_float2(out[u][nt][0] * inv0, out[u][nt][1] * inv0);
            *(float2*)&dst[(size_t)(rb + r + 8) * INNER_ + col] =
                make_float2(out[u][nt][2] * inv1, out[u][nt][3] * inv1);
        }
    }
}

// ---------------- K5: output projection, tf32 mma, 128x64 blocks ----------------
#define OPROJ_SMEM ((128 * 68 + 64 * 68) * 4)
__global__ void __launch_bounds__(256, 2) k_oproj(const float* __restrict__ wo,
                                                  const float* __restrict__ bo,
                                                  float* __restrict__ out) {
    extern __shared__ float smem[];
    float (*sA)[68] = (float(*)[68])(smem);
    float (*sW)[68] = (float(*)[68])(smem + 128 * 68);
    int row0 = blockIdx.x * 128;
    int o0   = blockIdx.y * 64;
    int tid  = threadIdx.x;
    int wid  = tid >> 5, lane = tid & 31;
    int r    = lane >> 2, t = lane & 3;
    int qb   = wid * 16;

    float s[8][4];
#pragma unroll
    for (int nt = 0; nt < 8; nt++)
#pragma unroll
        for (int c = 0; c < 4; c++) s[nt][c] = 0.f;

    for (int c0 = 0; c0 < INNER_; c0 += 64) {
#pragma unroll
        for (int it = 0; it < 8; it++) {
            int idx = tid + it * 256;
            int rr = idx >> 4, c4 = (idx & 15) * 4;
            float4 a4 = *(const float4*)&g_ao[(size_t)(row0 + rr) * INNER_ + c0 + c4];
            sA[rr][c4 + 0] = __uint_as_float(f2tf32(a4.x));
            sA[rr][c4 + 1] = __uint_as_float(f2tf32(a4.y));
            sA[rr][c4 + 2] = __uint_as_float(f2tf32(a4.z));
            sA[rr][c4 + 3] = __uint_as_float(f2tf32(a4.w));
        }
#pragma unroll
        for (int it = 0; it < 4; it++) {
            int idx = tid + it * 256;
            int rr = idx >> 4, c4 = (idx & 15) * 4;
            float4 w4 = *(const float4*)&wo[(size_t)(o0 + rr) * INNER_ + c0 + c4];
            sW[rr][c4 + 0] = __uint_as_float(f2tf32(w4.x));
            sW[rr][c4 + 1] = __uint_as_float(f2tf32(w4.y));
            sW[rr][c4 + 2] = __uint_as_float(f2tf32(w4.z));
            sW[rr][c4 + 3] = __uint_as_float(f2tf32(w4.w));
        }
        __syncthreads();
#pragma unroll
        for (int ks = 0; ks < 8; ks++) {
            int k0 = ks * 8;
            uint32_t a0 = __float_as_uint(sA[qb + r    ][k0 + t    ]);
            uint32_t a1 = __float_as_uint(sA[qb + r + 8][k0 + t    ]);
            uint32_t a2 = __float_as_uint(sA[qb + r    ][k0 + t + 4]);
            uint32_t a3 = __float_as_uint(sA[qb + r + 8][k0 + t + 4]);
#pragma unroll
            for (int nt = 0; nt < 8; nt++) {
                uint32_t b0 = __float_as_uint(sW[nt * 8 + r][k0 + t    ]);
                uint32_t b1 = __float_as_uint(sW[nt * 8 + r][k0 + t + 4]);
                mma_tf32(s[nt], a0, a1, a2, a3, b0, b1);
            }
        }
        __syncthreads();
    }

#pragma unroll
    for (int nt = 0; nt < 8; nt++) {
        int col = nt * 8 + 2 * t;
        int o = o0 + col;
        float b0 = bo[o], b1 = bo[o + 1];
        *(float2*)&out[(size_t)(row0 + qb + r    ) * D_ + o] =
            make_float2(s[nt][0] + b0, s[nt][1] + b1);
        *(float2*)&out[(size_t)(row0 + qb + r + 8) * D_ + o] =
            make_float2(s[nt][2] + b0, s[nt][3] + b1);
    }
}

// ---------------- launch ----------------
extern "C" void kernel_launch(void* const* d_in, const int* in_sizes, int n_in,
                              void* d_out, int out_size) {
    const float* x      = (const float*)d_in[0];
    const float* prev_x = (const float*)d_in[1];
    const float* wq     = (const float*)d_in[2];
    const float* wk     = (const float*)d_in[3];
    const float* wv     = (const float*)d_in[4];
    const float* wo     = (const float*)d_in[5];
    const float* bo     = (const float*)d_in[6];
    const float* w_off1 = (const float*)d_in[7];
    const float* b_off1 = (const float*)d_in[8];
    const float* w_off2 = (const float*)d_in[9];
    float* out = (float*)d_out;

    cudaFuncSetAttribute(k_attn,  cudaFuncAttributeMaxDynamicSharedMemorySize, ATTN_SMEM);
    cudaFuncSetAttribute(k_oproj, cudaFuncAttributeMaxDynamicSharedMemorySize, OPROJ_SMEM);

    k_qproj  <<<dim3(B_ * N_ / 64, G_), 256>>>(x, prev_x, wq);
    k_offsets<<<(B_ * G_ * M_) / 4, 256>>>(w_off1, b_off1, w_off2);
    k_kv     <<<(B_ * G_ * M_) / 8, 256>>>(prev_x, wk, wv);
    k_attn   <<<B_ * H_ * (N_ / 128), 128, ATTN_SMEM>>>();
    k_oproj  <<<dim3((B_ * N_) / 128, D_ / 64), 256, OPROJ_SMEM>>>(wo, bo, out);
}

// round 9
// speedup vs baseline: 14.4454x; 1.4203x over previous
#include <cuda_runtime.h>
#include <cuda_fp16.h>
#include <math.h>
#include <stdint.h>

// ---------------- constants (problem shapes are fixed) ----------------
#define B_   4
#define N_   4096
#define D_   256
#define H_   8
#define G_   8
#define DH_  64
#define INNER_ 512
#define M_   1024
#define KS_  6

// ---------------- tf32 mma helpers (k_oproj) ----------------
__device__ __forceinline__ uint32_t f2tf32(float f) {
    uint32_t r; asm("cvt.rna.tf32.f32 %0, %1;" : "=r"(r) : "f"(f)); return r;
}
__device__ __forceinline__ void mma_tf32(float* d,
                                         uint32_t a0, uint32_t a1, uint32_t a2, uint32_t a3,
                                         uint32_t b0, uint32_t b1) {
    asm("mma.sync.aligned.m16n8k8.row.col.f32.tf32.tf32.f32 "
        "{%0,%1,%2,%3}, {%4,%5,%6,%7}, {%8,%9}, {%0,%1,%2,%3};"
        : "+f"(d[0]), "+f"(d[1]), "+f"(d[2]), "+f"(d[3])
        : "r"(a0), "r"(a1), "r"(a2), "r"(a3), "r"(b0), "r"(b1));
}

// ---------------- fp16 mma helper (k_attn) ----------------
__device__ __forceinline__ void mma_f16(float* d,
                                        uint32_t a0, uint32_t a1, uint32_t a2, uint32_t a3,
                                        uint32_t b0, uint32_t b1) {
    asm("mma.sync.aligned.m16n8k16.row.col.f32.f16.f16.f32 "
        "{%0,%1,%2,%3}, {%4,%5,%6,%7}, {%8,%9}, {%0,%1,%2,%3};"
        : "+f"(d[0]), "+f"(d[1]), "+f"(d[2]), "+f"(d[3])
        : "r"(a0), "r"(a1), "r"(a2), "r"(a3), "r"(b0), "r"(b1));
}

// ---------------- scratch ----------------
__device__ float g_q  [B_ * N_ * INNER_];
__device__ float g_pos[B_ * G_ * M_];
__device__ float g_k  [B_ * M_ * INNER_];
__device__ float g_vt [B_ * H_ * DH_ * M_];   // transposed V: [b][h][d][m]
__device__ float g_ao [B_ * N_ * INNER_];

// ---------------- K1: q = grouped conv1x1, GEMM-tiled per group ----------------
__global__ __launch_bounds__(256) void k_qproj(const float* __restrict__ x,
                                               const float* __restrict__ px,
                                               const float* __restrict__ wq) {
    __shared__ float sIn[64][68];
    __shared__ float sW [64][68];
    int tok0 = blockIdx.x * 64;
    int g    = blockIdx.y;
    int tid  = threadIdx.x;
    int ty = tid >> 4, tx = tid & 15;

    const float* src = (g < 4) ? px : x;
    int cb = (g & 3) * 64;

#pragma unroll
    for (int it = 0; it < 4; it++) {
        int idx = tid + it * 256;
        int r = idx >> 4, c4 = (idx & 15) * 4;
        *(float4*)&sIn[r][c4] = *(const float4*)&src[(size_t)(tok0 + r) * D_ + cb + c4];
        *(float4*)&sW [r][c4] = *(const float4*)&wq [(size_t)(g * 64 + r) * 64 + c4];
    }
    __syncthreads();

    float acc[4][4];
#pragma unroll
    for (int i = 0; i < 4; i++)
#pragma unroll
        for (int j = 0; j < 4; j++) acc[i][j] = 0.f;

#pragma unroll
    for (int d0 = 0; d0 < 64; d0 += 4) {
        float4 av[4], wv[4];
#pragma unroll
        for (int i = 0; i < 4; i++) av[i] = *(const float4*)&sIn[ty + 16 * i][d0];
#pragma unroll
        for (int j = 0; j < 4; j++) wv[j] = *(const float4*)&sW[tx + 16 * j][d0];
#pragma unroll
        for (int i = 0; i < 4; i++)
#pragma unroll
            for (int j = 0; j < 4; j++) {
                acc[i][j] = fmaf(av[i].x, wv[j].x, acc[i][j]);
                acc[i][j] = fmaf(av[i].y, wv[j].y, acc[i][j]);
                acc[i][j] = fmaf(av[i].z, wv[j].z, acc[i][j]);
                acc[i][j] = fmaf(av[i].w, wv[j].w, acc[i][j]);
            }
    }
#pragma unroll
    for (int i = 0; i < 4; i++)
#pragma unroll
        for (int j = 0; j < 4; j++)
            g_q[(size_t)(tok0 + ty + 16 * i) * INNER_ + g * 64 + tx + 16 * j] = acc[i][j];
}

// ---------------- K2: offsets -> sampling positions ----------------
__global__ __launch_bounds__(256) void k_offsets(const float* __restrict__ w1,
                                                 const float* __restrict__ b1,
                                                 const float* __restrict__ w2) {
    __shared__ float red[8];
    int tid = threadIdx.x;
    int p = blockIdx.x * 4 + (tid >> 6);
    int c = tid & 63;
    int bc = p >> 10, m = p & (M_ - 1);
    int b = bc >> 3, g = bc & 7;
    const float* qbase = g_q + (size_t)b * N_ * INNER_ + g * 64 + c;

    float h = b1[c];
    int n0 = 4 * m - 1;
#pragma unroll
    for (int k = 0; k < KS_; k++) {
        int n = n0 + k;
        if (n >= 0 && n < N_) h = fmaf(qbase[(size_t)n * INNER_], w1[c * KS_ + k], h);
    }
    float ge  = 0.5f * h * (1.f + erff(h * 0.70710678118654752f));
    float val = ge * w2[c];
#pragma unroll
    for (int o = 16; o > 0; o >>= 1) val += __shfl_xor_sync(0xffffffffu, val, o);
    if ((tid & 31) == 0) red[tid >> 5] = val;
    __syncthreads();
    if (tid < 4) {
        float off = tanhf(red[2 * tid] + red[2 * tid + 1]) * 4.0f;
        int pp = blockIdx.x * 4 + tid;
        int mm = pp & (M_ - 1);
        g_pos[pp] = ((float)mm + off) * ((float)N_ / (float)(M_ - 1)) - 0.5f;
    }
}

// ---------------- K3: gather + k/v conv1x1; K normal layout, V transposed ----------------
__global__ __launch_bounds__(256) void k_kv(const float* __restrict__ px,
                                            const float* __restrict__ wk,
                                            const float* __restrict__ wv) {
    __shared__ float skv[32][33];       // [ch][m] transposed gather
    __shared__ float sW [128][33];      // rows 0..63 wk, 64..127 wv
    int blk = blockIdx.x;               // B*G*(M/32) = 1024 blocks
    int bc  = blk >> 5;
    int m0  = (blk & 31) * 32;
    int b = bc >> 3, g = bc & 7;
    int tid = threadIdx.x;

#pragma unroll
    for (int it = 0; it < 16; it++) {
        int idx = tid + it * 256;
        int row = idx >> 5, d = idx & 31;
        const float* w = (row < 64) ? wk : wv;
        sW[row][d] = w[(size_t)(g * 64 + (row & 63)) * 32 + d];
    }

#pragma unroll
    for (int it = 0; it < 4; it++) {
        int idx = tid + it * 256;       // 1024 = 32m x 32ch
        int m = idx & 31, ch = idx >> 5;
        float pos = g_pos[bc * M_ + m0 + m];
        float fp  = floorf(pos);
        int   i0  = (int)fp;
        float w1f = pos - fp;
        const float* base = px + (size_t)b * N_ * D_ + g * 32 + ch;
        float v0 = (i0 >= 0     && i0     < N_) ? base[(size_t)i0 * D_]       : 0.f;
        float v1 = (i0 + 1 >= 0 && i0 + 1 < N_) ? base[(size_t)(i0 + 1) * D_] : 0.f;
        skv[ch][m] = v0 * (1.f - w1f) + v1 * w1f;
    }
    __syncthreads();

    // K pass: lanes = o (coalesced g_k writes), skv row broadcast
#pragma unroll
    for (int u = 0; u < 8; u++) {
        int idx = tid + u * 256;        // 2048 = 32m x 64o
        int o = idx & 63, msub = idx >> 6;
        float acc = 0.f;
#pragma unroll
        for (int d = 0; d < 32; d++) acc = fmaf(skv[d][msub], sW[o][d], acc);
        g_k[((size_t)b * M_ + m0 + msub) * INNER_ + g * 64 + o] = acc;
    }
    // V pass: lanes = m (coalesced g_vt writes), sW broadcast
#pragma unroll
    for (int u = 0; u < 8; u++) {
        int idx = tid + u * 256;
        int m = idx & 31, o = idx >> 5;
        float acc = 0.f;
#pragma unroll
        for (int d = 0; d < 32; d++) acc = fmaf(skv[d][m], sW[64 + o][d], acc);
        g_vt[((size_t)(b * 8 + g) * 64 + o) * M_ + m0 + m] = acc;
    }
}

// ---------------- K4: flash attention, fp16 m16n8k16, 4 warps x 32 q-rows ----------------
// smem (half, row stride 72 halves = 36 u32): Q[128] | K(64)/P(128) alias | Vt[64]
#define ATTN_SMEM ((128 * 36 + 128 * 36 + 64 * 36) * 4)
__global__ void __launch_bounds__(128, 3) k_attn() {
    int blk = blockIdx.x;            // b*256 + h*32 + qt
    int qt = blk & 31;
    int h  = (blk >> 5) & 7;
    int b  = blk >> 8;
    int n0 = qt << 7;

    extern __shared__ uint32_t smem[];
    uint32_t* sQ  = smem;                 // 128 x 36 u32
    uint32_t* sKP = smem + 128 * 36;      // K rows 0..63 / P rows 0..127
    uint32_t* sVt = smem + 256 * 36;      // 64 x 36 u32  (Vt[d][m])
    __half2* sQh  = (__half2*)sQ;
    __half2* sKPh = (__half2*)sKP;
    __half2* sVth = (__half2*)sVt;

    int tid  = threadIdx.x;
    int wid  = tid >> 5, lane = tid & 31;
    int r    = lane >> 2, t = lane & 3;
    int qb   = wid * 32;                 // 32 q rows per warp

    // ---- load Q (scaled, fp16) ----
    const float* qsrc = g_q + ((size_t)b * N_ + n0) * INNER_ + h * 64;
#pragma unroll
    for (int it = 0; it < 16; it++) {
        int idx = tid + it * 128;
        int rr = idx >> 4, c = idx & 15;
        float4 qv = *(const float4*)&qsrc[(size_t)rr * INNER_ + c * 4];
        sQh[rr * 36 + c * 2    ] = __floats2half2_rn(qv.x * 0.125f, qv.y * 0.125f);
        sQh[rr * 36 + c * 2 + 1] = __floats2half2_rn(qv.z * 0.125f, qv.w * 0.125f);
    }

    float out[2][8][4];
#pragma unroll
    for (int u = 0; u < 2; u++)
#pragma unroll
        for (int nt = 0; nt < 8; nt++)
#pragma unroll
            for (int c = 0; c < 4; c++) out[u][nt][c] = 0.f;
    float rmax[2][2], rsum[2][2];
#pragma unroll
    for (int u = 0; u < 2; u++) { rmax[u][0] = rmax[u][1] = -1e30f; rsum[u][0] = rsum[u][1] = 0.f; }

    const float* kbase  = g_k  + ((size_t)b * M_) * INNER_ + h * 64;
    const float* vtbase = g_vt + ((size_t)(b * 8 + h) * 64) * M_;
    __syncthreads();

    for (int kt = 0; kt < 16; kt++) {
        int m0 = kt << 6;
        // ---- load K (rows m, cols d) and Vt (rows d, cols m), fp16 ----
#pragma unroll
        for (int it = 0; it < 8; it++) {
            int idx = tid + it * 128;
            int rr = idx >> 4, c = idx & 15;
            float4 k4 = *(const float4*)&kbase[(size_t)(m0 + rr) * INNER_ + c * 4];
            sKPh[rr * 36 + c * 2    ] = __floats2half2_rn(k4.x, k4.y);
            sKPh[rr * 36 + c * 2 + 1] = __floats2half2_rn(k4.z, k4.w);
            float4 v4 = *(const float4*)&vtbase[(size_t)rr * M_ + m0 + c * 4];
            sVth[rr * 36 + c * 2    ] = __floats2half2_rn(v4.x, v4.y);
            sVth[rr * 36 + c * 2 + 1] = __floats2half2_rn(v4.z, v4.w);
        }
        __syncthreads();

        // ---- QK^T : S[32 x 64] per warp, k16 steps ----
        float s[2][8][4];
#pragma unroll
        for (int u = 0; u < 2; u++)
#pragma unroll
            for (int nt = 0; nt < 8; nt++)
#pragma unroll
                for (int c = 0; c < 4; c++) s[u][nt][c] = 0.f;

#pragma unroll
        for (int ks = 0; ks < 4; ks++) {
            int kb = ks * 8;
            uint32_t a[2][4];
#pragma unroll
            for (int u = 0; u < 2; u++) {
                int rb = qb + u * 16;
                a[u][0] = sQ[(rb + r    ) * 36 + kb + t    ];
                a[u][1] = sQ[(rb + r + 8) * 36 + kb + t    ];
                a[u][2] = sQ[(rb + r    ) * 36 + kb + t + 4];
                a[u][3] = sQ[(rb + r + 8) * 36 + kb + t + 4];
            }
#pragma unroll
            for (int nt = 0; nt < 8; nt++) {
                uint32_t b0 = sKP[(nt * 8 + r) * 36 + kb + t    ];
                uint32_t b1 = sKP[(nt * 8 + r) * 36 + kb + t + 4];
                mma_f16(s[0][nt], a[0][0], a[0][1], a[0][2], a[0][3], b0, b1);
                mma_f16(s[1][nt], a[1][0], a[1][1], a[1][2], a[1][3], b0, b1);
            }
        }
        __syncthreads();   // all warps done reading K before P overwrites

        // ---- online softmax (two row-tiles per warp) ----
#pragma unroll
        for (int u = 0; u < 2; u++) {
            int rb = qb + u * 16;
            float lm0 = -1e30f, lm1 = -1e30f;
#pragma unroll
            for (int nt = 0; nt < 8; nt++) {
                lm0 = fmaxf(lm0, fmaxf(s[u][nt][0], s[u][nt][1]));
                lm1 = fmaxf(lm1, fmaxf(s[u][nt][2], s[u][nt][3]));
            }
            lm0 = fmaxf(lm0, __shfl_xor_sync(0xffffffffu, lm0, 1));
            lm0 = fmaxf(lm0, __shfl_xor_sync(0xffffffffu, lm0, 2));
            lm1 = fmaxf(lm1, __shfl_xor_sync(0xffffffffu, lm1, 1));
            lm1 = fmaxf(lm1, __shfl_xor_sync(0xffffffffu, lm1, 2));
            float nm0 = fmaxf(rmax[u][0], lm0), nm1 = fmaxf(rmax[u][1], lm1);
            float f0 = __expf(rmax[u][0] - nm0), f1 = __expf(rmax[u][1] - nm1);
            rmax[u][0] = nm0; rmax[u][1] = nm1;
            float ls0 = 0.f, ls1 = 0.f;
#pragma unroll
            for (int nt = 0; nt < 8; nt++) {
                float p00 = __expf(s[u][nt][0] - nm0);
                float p01 = __expf(s[u][nt][1] - nm0);
                float p10 = __expf(s[u][nt][2] - nm1);
                float p11 = __expf(s[u][nt][3] - nm1);
                ls0 += p00 + p01; ls1 += p10 + p11;
                sKPh[(rb + r    ) * 36 + nt * 4 + t] = __floats2half2_rn(p00, p01);
                sKPh[(rb + r + 8) * 36 + nt * 4 + t] = __floats2half2_rn(p10, p11);
            }
            ls0 += __shfl_xor_sync(0xffffffffu, ls0, 1);
            ls0 += __shfl_xor_sync(0xffffffffu, ls0, 2);
            ls1 += __shfl_xor_sync(0xffffffffu, ls1, 1);
            ls1 += __shfl_xor_sync(0xffffffffu, ls1, 2);
            rsum[u][0] = rsum[u][0] * f0 + ls0;
            rsum[u][1] = rsum[u][1] * f1 + ls1;
#pragma unroll
            for (int nt = 0; nt < 8; nt++) {
                out[u][nt][0] *= f0; out[u][nt][1] *= f0;
                out[u][nt][2] *= f1; out[u][nt][3] *= f1;
            }
        }
        __syncwarp();      // own P rows written before own A-frag reads

        // ---- P @ V (B from transposed V) ----
#pragma unroll
        for (int ks = 0; ks < 4; ks++) {
            int kb = ks * 8;
            uint32_t a[2][4];
#pragma unroll
            for (int u = 0; u < 2; u++) {
                int rb = qb + u * 16;
                a[u][0] = sKP[(rb + r    ) * 36 + kb + t    ];
                a[u][1] = sKP[(rb + r + 8) * 36 + kb + t    ];
                a[u][2] = sKP[(rb + r    ) * 36 + kb + t + 4];
                a[u][3] = sKP[(rb + r + 8) * 36 + kb + t + 4];
            }
#pragma unroll
            for (int nt = 0; nt < 8; nt++) {
                uint32_t b0 = sVt[(nt * 8 + r) * 36 + kb + t    ];
                uint32_t b1 = sVt[(nt * 8 + r) * 36 + kb + t + 4];
                mma_f16(out[0][nt], a[0][0], a[0][1], a[0][2], a[0][3], b0, b1);
                mma_f16(out[1][nt], a[1][0], a[1][1], a[1][2], a[1][3], b0, b1);
            }
        }
        __syncthreads();   // done reading sVt/sP before next tile load
    }

    // ---- epilogue ----
    float* dst = g_ao + ((size_t)b * N_ + n0) * INNER_ + h * 64;
#pragma unroll
    for (int u = 0; u < 2; u++) {
        int rb = qb + u * 16;
        float inv0 = 1.f / rsum[u][0], inv1 = 1.f / rsum[u][1];
#pragma unroll
        for (int nt = 0; nt < 8; nt++) {
            int col = nt * 8 + 2 * t;
            *(float2*)&dst[(size_t)(rb + r    ) * INNER_ + col] =
                make_float2(out[u][nt][0] * inv0, out[u][nt][1] * inv0);
            *(float2*)&dst[(size_t)(rb + r + 8) * INNER_ + col] =
                make_float2(out[u][nt][2] * inv1, out[u][nt][3] * inv1);
        }
    }
}

// ---------------- K5: output projection, tf32 mma, 128x64 blocks ----------------
#define OPROJ_SMEM ((128 * 68 + 64 * 68) * 4)
__global__ void __launch_bounds__(256, 2) k_oproj(const float* __restrict__ wo,
                                                  const float* __restrict__ bo,
                                                  float* __restrict__ out) {
    extern __shared__ float smemf[];
    float (*sA)[68] = (float(*)[68])(smemf);
    float (*sW)[68] = (float(*)[68])(smemf + 128 * 68);
    int row0 = blockIdx.x * 128;
    int o0   = blockIdx.y * 64;
    int tid  = threadIdx.x;
    int wid  = tid >> 5, lane = tid & 31;
    int r    = lane >> 2, t = lane & 3;
    int qb   = wid * 16;

    float s[8][4];
#pragma unroll
    for (int nt = 0; nt < 8; nt++)
#pragma unroll
        for (int c = 0; c < 4; c++) s[nt][c] = 0.f;

    for (int c0 = 0; c0 < INNER_; c0 += 64) {
#pragma unroll
        for (int it = 0; it < 8; it++) {
            int idx = tid + it * 256;
            int rr = idx >> 4, c4 = (idx & 15) * 4;
            float4 a4 = *(const float4*)&g_ao[(size_t)(row0 + rr) * INNER_ + c0 + c4];
            sA[rr][c4 + 0] = __uint_as_float(f2tf32(a4.x));
            sA[rr][c4 + 1] = __uint_as_float(f2tf32(a4.y));
            sA[rr][c4 + 2] = __uint_as_float(f2tf32(a4.z));
            sA[rr][c4 + 3] = __uint_as_float(f2tf32(a4.w));
        }
#pragma unroll
        for (int it = 0; it < 4; it++) {
            int idx = tid + it * 256;
            int rr = idx >> 4, c4 = (idx & 15) * 4;
            float4 w4 = *(const float4*)&wo[(size_t)(o0 + rr) * INNER_ + c0 + c4];
            sW[rr][c4 + 0] = __uint_as_float(f2tf32(w4.x));
            sW[rr][c4 + 1] = __uint_as_float(f2tf32(w4.y));
            sW[rr][c4 + 2] = __uint_as_float(f2tf32(w4.z));
            sW[rr][c4 + 3] = __uint_as_float(f2tf32(w4.w));
        }
        __syncthreads();
#pragma unroll
        for (int ks = 0; ks < 8; ks++) {
            int k0 = ks * 8;
            uint32_t a0 = __float_as_uint(sA[qb + r    ][k0 + t    ]);
            uint32_t a1 = __float_as_uint(sA[qb + r + 8][k0 + t    ]);
            uint32_t a2 = __float_as_uint(sA[qb + r    ][k0 + t + 4]);
            uint32_t a3 = __float_as_uint(sA[qb + r + 8][k0 + t + 4]);
#pragma unroll
            for (int nt = 0; nt < 8; nt++) {
                uint32_t b0 = __float_as_uint(sW[nt * 8 + r][k0 + t    ]);
                uint32_t b1 = __float_as_uint(sW[nt * 8 + r][k0 + t + 4]);
                mma_tf32(s[nt], a0, a1, a2, a3, b0, b1);
            }
        }
        __syncthreads();
    }

#pragma unroll
    for (int nt = 0; nt < 8; nt++) {
        int col = nt * 8 + 2 * t;
        int o = o0 + col;
        float b0 = bo[o], b1 = bo[o + 1];
        *(float2*)&out[(size_t)(row0 + qb + r    ) * D_ + o] =
            make_float2(s[nt][0] + b0, s[nt][1] + b1);
        *(float2*)&out[(size_t)(row0 + qb + r + 8) * D_ + o] =
            make_float2(s[nt][2] + b0, s[nt][3] + b1);
    }
}

// ---------------- launch ----------------
extern "C" void kernel_launch(void* const* d_in, const int* in_sizes, int n_in,
                              void* d_out, int out_size) {
    const float* x      = (const float*)d_in[0];
    const float* prev_x = (const float*)d_in[1];
    const float* wq     = (const float*)d_in[2];
    const float* wk     = (const float*)d_in[3];
    const float* wv     = (const float*)d_in[4];
    const float* wo     = (const float*)d_in[5];
    const float* bo     = (const float*)d_in[6];
    const float* w_off1 = (const float*)d_in[7];
    const float* b_off1 = (const float*)d_in[8];
    const float* w_off2 = (const float*)d_in[9];
    float* out = (float*)d_out;

    cudaFuncSetAttribute(k_attn,  cudaFuncAttributeMaxDynamicSharedMemorySize, ATTN_SMEM);
    cudaFuncSetAttribute(k_oproj, cudaFuncAttributeMaxDynamicSharedMemorySize, OPROJ_SMEM);

    k_qproj  <<<dim3(B_ * N_ / 64, G_), 256>>>(x, prev_x, wq);
    k_offsets<<<(B_ * G_ * M_) / 4, 256>>>(w_off1, b_off1, w_off2);
    k_kv     <<<(B_ * G_ * M_) / 32, 256>>>(prev_x, wk, wv);
    k_attn   <<<B_ * H_ * (N_ / 128), 128, ATTN_SMEM>>>();
    k_oproj  <<<dim3((B_ * N_) / 128, D_ / 64), 256, OPROJ_SMEM>>>(wo, bo, out);
}

// round 10
// speedup vs baseline: 15.7958x; 1.0935x over previous
#include <cuda_runtime.h>
#include <cuda_fp16.h>
#include <math.h>
#include <stdint.h>

// ---------------- constants (problem shapes are fixed) ----------------
#define B_   4
#define N_   4096
#define D_   256
#define H_   8
#define G_   8
#define DH_  64
#define INNER_ 512
#define M_   1024
#define KS_  6
#define QSCALE 0.1803368801111f   // 0.125 * log2(e)  (exp2-domain softmax)

// ---------------- tf32 mma helpers (k_oproj) ----------------
__device__ __forceinline__ uint32_t f2tf32(float f) {
    uint32_t r; asm("cvt.rna.tf32.f32 %0, %1;" : "=r"(r) : "f"(f)); return r;
}
__device__ __forceinline__ void mma_tf32(float* d,
                                         uint32_t a0, uint32_t a1, uint32_t a2, uint32_t a3,
                                         uint32_t b0, uint32_t b1) {
    asm("mma.sync.aligned.m16n8k8.row.col.f32.tf32.tf32.f32 "
        "{%0,%1,%2,%3}, {%4,%5,%6,%7}, {%8,%9}, {%0,%1,%2,%3};"
        : "+f"(d[0]), "+f"(d[1]), "+f"(d[2]), "+f"(d[3])
        : "r"(a0), "r"(a1), "r"(a2), "r"(a3), "r"(b0), "r"(b1));
}

// ---------------- fp16 mma helper (k_attn) ----------------
__device__ __forceinline__ void mma_f16(float* d,
                                        uint32_t a0, uint32_t a1, uint32_t a2, uint32_t a3,
                                        uint32_t b0, uint32_t b1) {
    asm("mma.sync.aligned.m16n8k16.row.col.f32.f16.f16.f32 "
        "{%0,%1,%2,%3}, {%4,%5,%6,%7}, {%8,%9}, {%0,%1,%2,%3};"
        : "+f"(d[0]), "+f"(d[1]), "+f"(d[2]), "+f"(d[3])
        : "r"(a0), "r"(a1), "r"(a2), "r"(a3), "r"(b0), "r"(b1));
}

__device__ __forceinline__ uint32_t cvta_smem(const void* p) {
    return (uint32_t)__cvta_generic_to_shared(p);
}
#define CP_A16(dst_u32, src_ptr) \
    asm volatile("cp.async.cg.shared.global [%0], [%1], 16;" :: "r"(dst_u32), "l"(src_ptr))

// ---------------- scratch ----------------
__device__ float  g_q  [B_ * N_ * INNER_];      // fp32 q (for offsets)
__device__ __half g_qh [B_ * N_ * INNER_];      // fp16 q, pre-scaled by QSCALE
__device__ float  g_pos[B_ * G_ * M_];
__device__ __half g_kh [B_ * M_ * INNER_];      // fp16 k
__device__ __half g_vth[B_ * H_ * DH_ * M_];    // fp16 transposed V: [b][h][d][m]
__device__ float  g_ao [B_ * N_ * INNER_];

// ---------------- K1: q = grouped conv1x1, GEMM-tiled per group ----------------
__global__ __launch_bounds__(256) void k_qproj(const float* __restrict__ x,
                                               const float* __restrict__ px,
                                               const float* __restrict__ wq) {
    __shared__ float sIn[64][68];
    __shared__ float sW [64][68];
    int tok0 = blockIdx.x * 64;
    int g    = blockIdx.y;
    int tid  = threadIdx.x;
    int ty = tid >> 4, tx = tid & 15;

    const float* src = (g < 4) ? px : x;
    int cb = (g & 3) * 64;

#pragma unroll
    for (int it = 0; it < 4; it++) {
        int idx = tid + it * 256;
        int r = idx >> 4, c4 = (idx & 15) * 4;
        *(float4*)&sIn[r][c4] = *(const float4*)&src[(size_t)(tok0 + r) * D_ + cb + c4];
        *(float4*)&sW [r][c4] = *(const float4*)&wq [(size_t)(g * 64 + r) * 64 + c4];
    }
    __syncthreads();

    float acc[4][4];
#pragma unroll
    for (int i = 0; i < 4; i++)
#pragma unroll
        for (int j = 0; j < 4; j++) acc[i][j] = 0.f;

#pragma unroll
    for (int d0 = 0; d0 < 64; d0 += 4) {
        float4 av[4], wv[4];
#pragma unroll
        for (int i = 0; i < 4; i++) av[i] = *(const float4*)&sIn[ty + 16 * i][d0];
#pragma unroll
        for (int j = 0; j < 4; j++) wv[j] = *(const float4*)&sW[tx + 16 * j][d0];
#pragma unroll
        for (int i = 0; i < 4; i++)
#pragma unroll
            for (int j = 0; j < 4; j++) {
                acc[i][j] = fmaf(av[i].x, wv[j].x, acc[i][j]);
                acc[i][j] = fmaf(av[i].y, wv[j].y, acc[i][j]);
                acc[i][j] = fmaf(av[i].z, wv[j].z, acc[i][j]);
                acc[i][j] = fmaf(av[i].w, wv[j].w, acc[i][j]);
            }
    }
#pragma unroll
    for (int i = 0; i < 4; i++)
#pragma unroll
        for (int j = 0; j < 4; j++) {
            size_t o = (size_t)(tok0 + ty + 16 * i) * INNER_ + g * 64 + tx + 16 * j;
            g_q [o] = acc[i][j];
            g_qh[o] = __float2half_rn(acc[i][j] * QSCALE);
        }
}

// ---------------- K2: offsets -> sampling positions ----------------
__global__ __launch_bounds__(256) void k_offsets(const float* __restrict__ w1,
                                                 const float* __restrict__ b1,
                                                 const float* __restrict__ w2) {
    __shared__ float red[8];
    int tid = threadIdx.x;
    int p = blockIdx.x * 4 + (tid >> 6);
    int c = tid & 63;
    int bc = p >> 10, m = p & (M_ - 1);
    int b = bc >> 3, g = bc & 7;
    const float* qbase = g_q + (size_t)b * N_ * INNER_ + g * 64 + c;

    float h = b1[c];
    int n0 = 4 * m - 1;
#pragma unroll
    for (int k = 0; k < KS_; k++) {
        int n = n0 + k;
        if (n >= 0 && n < N_) h = fmaf(qbase[(size_t)n * INNER_], w1[c * KS_ + k], h);
    }
    float ge  = 0.5f * h * (1.f + erff(h * 0.70710678118654752f));
    float val = ge * w2[c];
#pragma unroll
    for (int o = 16; o > 0; o >>= 1) val += __shfl_xor_sync(0xffffffffu, val, o);
    if ((tid & 31) == 0) red[tid >> 5] = val;
    __syncthreads();
    if (tid < 4) {
        float off = tanhf(red[2 * tid] + red[2 * tid + 1]) * 4.0f;
        int pp = blockIdx.x * 4 + tid;
        int mm = pp & (M_ - 1);
        g_pos[pp] = ((float)mm + off) * ((float)N_ / (float)(M_ - 1)) - 0.5f;
    }
}

// ---------------- K3: gather + k/v conv1x1; K fp16, V fp16 transposed ----------------
__global__ __launch_bounds__(256) void k_kv(const float* __restrict__ px,
                                            const float* __restrict__ wk,
                                            const float* __restrict__ wv) {
    __shared__ float skv[32][33];       // [ch][m]
    __shared__ float sW [128][33];
    int blk = blockIdx.x;               // B*G*(M/32) = 1024 blocks
    int bc  = blk >> 5;
    int m0  = (blk & 31) * 32;
    int b = bc >> 3, g = bc & 7;
    int tid = threadIdx.x;

#pragma unroll
    for (int it = 0; it < 16; it++) {
        int idx = tid + it * 256;
        int row = idx >> 5, d = idx & 31;
        const float* w = (row < 64) ? wk : wv;
        sW[row][d] = w[(size_t)(g * 64 + (row & 63)) * 32 + d];
    }

#pragma unroll
    for (int it = 0; it < 4; it++) {
        int idx = tid + it * 256;
        int m = idx & 31, ch = idx >> 5;
        float pos = g_pos[bc * M_ + m0 + m];
        float fp  = floorf(pos);
        int   i0  = (int)fp;
        float w1f = pos - fp;
        const float* base = px + (size_t)b * N_ * D_ + g * 32 + ch;
        float v0 = (i0 >= 0     && i0     < N_) ? base[(size_t)i0 * D_]       : 0.f;
        float v1 = (i0 + 1 >= 0 && i0 + 1 < N_) ? base[(size_t)(i0 + 1) * D_] : 0.f;
        skv[ch][m] = v0 * (1.f - w1f) + v1 * w1f;
    }
    __syncthreads();

    // K pass: coalesced half writes over o
#pragma unroll
    for (int u = 0; u < 8; u++) {
        int idx = tid + u * 256;
        int o = idx & 63, msub = idx >> 6;
        float acc = 0.f;
#pragma unroll
        for (int d = 0; d < 32; d++) acc = fmaf(skv[d][msub], sW[o][d], acc);
        g_kh[((size_t)b * M_ + m0 + msub) * INNER_ + g * 64 + o] = __float2half_rn(acc);
    }
    // V pass: coalesced half writes over m (transposed layout)
#pragma unroll
    for (int u = 0; u < 8; u++) {
        int idx = tid + u * 256;
        int m = idx & 31, o = idx >> 5;
        float acc = 0.f;
#pragma unroll
        for (int d = 0; d < 32; d++) acc = fmaf(skv[d][m], sW[64 + o][d], acc);
        g_vth[((size_t)(b * 8 + g) * 64 + o) * M_ + m0 + m] = __float2half_rn(acc);
    }
}

// ---------------- K4: flash attention, fp16 mma, cp.async double buffer ----------------
// smem u32: Q[128*36] | K 2x[64*36] | Vt 2x[64*36] | P[128*36]   (stride 36 u32 = 72 halves)
#define ATTN_SMEM ((128 * 36 + 4 * 64 * 36 + 128 * 36) * 4)
__global__ void __launch_bounds__(128, 3) k_attn() {
    int blk = blockIdx.x;            // b*256 + h*32 + qt
    int qt = blk & 31;
    int h  = (blk >> 5) & 7;
    int b  = blk >> 8;
    int n0 = qt << 7;

    extern __shared__ uint32_t smem[];
    uint32_t* sQ  = smem;                         // 128*36
    uint32_t* sK  = smem + 128 * 36;              // 2 x 64*36
    uint32_t* sVt = smem + 128 * 36 + 2 * 64 * 36;
    uint32_t* sP  = smem + 128 * 36 + 4 * 64 * 36;
    __half2*  sPh = (__half2*)sP;

    int tid  = threadIdx.x;
    int wid  = tid >> 5, lane = tid & 31;
    int r    = lane >> 2, t = lane & 3;
    int qb   = wid * 32;

    const __half* qsrc   = g_qh  + ((size_t)b * N_ + n0) * INNER_ + h * 64;
    const __half* kbase  = g_kh  + ((size_t)b * M_) * INNER_ + h * 64;
    const __half* vtbase = g_vth + ((size_t)(b * 8 + h) * 64) * M_;

    // ---- stage Q (pre-scaled fp16) ----
#pragma unroll
    for (int it = 0; it < 8; it++) {
        int idx = tid + it * 128;
        int rr = idx >> 3, c = idx & 7;
        *(uint4*)&sQ[rr * 36 + c * 4] = *(const uint4*)(qsrc + (size_t)rr * INNER_ + c * 8);
    }

    uint32_t sKaddr = cvta_smem(sK);
    uint32_t sVaddr = cvta_smem(sVt);
    auto load_tile = [&](int kt, int buf) {
        int m0 = kt << 6;
#pragma unroll
        for (int it = 0; it < 4; it++) {
            int idx = tid + it * 128;
            int rr = idx >> 3, c = idx & 7;
            CP_A16(sKaddr + (uint32_t)(buf * 64 * 36 + rr * 36 + c * 4) * 4,
                   kbase + (size_t)(m0 + rr) * INNER_ + c * 8);
        }
#pragma unroll
        for (int it = 0; it < 4; it++) {
            int idx = tid + it * 128;
            int rr = idx >> 3, c = idx & 7;
            CP_A16(sVaddr + (uint32_t)(buf * 64 * 36 + rr * 36 + c * 4) * 4,
                   vtbase + (size_t)rr * M_ + m0 + c * 8);
        }
    };

    float out[2][8][4];
#pragma unroll
    for (int u = 0; u < 2; u++)
#pragma unroll
        for (int nt = 0; nt < 8; nt++)
#pragma unroll
            for (int c = 0; c < 4; c++) out[u][nt][c] = 0.f;
    float rmax[2][2], rsum[2][2];
#pragma unroll
    for (int u = 0; u < 2; u++) { rmax[u][0] = rmax[u][1] = -1e30f; rsum[u][0] = rsum[u][1] = 0.f; }

    load_tile(0, 0);
    asm volatile("cp.async.commit_group;");

    for (int kt = 0; kt < 16; kt++) {
        int buf = kt & 1;
        if (kt < 15) {
            load_tile(kt + 1, buf ^ 1);
            asm volatile("cp.async.commit_group;");
            asm volatile("cp.async.wait_group 1;");
        } else {
            asm volatile("cp.async.wait_group 0;");
        }
        __syncthreads();

        uint32_t* sKb  = sK  + buf * 64 * 36;
        uint32_t* sVtb = sVt + buf * 64 * 36;

        // ---- QK^T ----
        float s[2][8][4];
#pragma unroll
        for (int u = 0; u < 2; u++)
#pragma unroll
            for (int nt = 0; nt < 8; nt++)
#pragma unroll
                for (int c = 0; c < 4; c++) s[u][nt][c] = 0.f;

#pragma unroll
        for (int ks = 0; ks < 4; ks++) {
            int kb = ks * 8;
            uint32_t a[2][4];
#pragma unroll
            for (int u = 0; u < 2; u++) {
                int rb = qb + u * 16;
                a[u][0] = sQ[(rb + r    ) * 36 + kb + t    ];
                a[u][1] = sQ[(rb + r + 8) * 36 + kb + t    ];
                a[u][2] = sQ[(rb + r    ) * 36 + kb + t + 4];
                a[u][3] = sQ[(rb + r + 8) * 36 + kb + t + 4];
            }
#pragma unroll
            for (int nt = 0; nt < 8; nt++) {
                uint32_t b0 = sKb[(nt * 8 + r) * 36 + kb + t    ];
                uint32_t b1 = sKb[(nt * 8 + r) * 36 + kb + t + 4];
                mma_f16(s[0][nt], a[0][0], a[0][1], a[0][2], a[0][3], b0, b1);
                mma_f16(s[1][nt], a[1][0], a[1][1], a[1][2], a[1][3], b0, b1);
            }
        }

        // ---- online softmax (exp2 domain), per-warp only ----
#pragma unroll
        for (int u = 0; u < 2; u++) {
            int rb = qb + u * 16;
            float lm0 = -1e30f, lm1 = -1e30f;
#pragma unroll
            for (int nt = 0; nt < 8; nt++) {
                lm0 = fmaxf(lm0, fmaxf(s[u][nt][0], s[u][nt][1]));
                lm1 = fmaxf(lm1, fmaxf(s[u][nt][2], s[u][nt][3]));
            }
            lm0 = fmaxf(lm0, __shfl_xor_sync(0xffffffffu, lm0, 1));
            lm0 = fmaxf(lm0, __shfl_xor_sync(0xffffffffu, lm0, 2));
            lm1 = fmaxf(lm1, __shfl_xor_sync(0xffffffffu, lm1, 1));
            lm1 = fmaxf(lm1, __shfl_xor_sync(0xffffffffu, lm1, 2));
            float nm0 = fmaxf(rmax[u][0], lm0), nm1 = fmaxf(rmax[u][1], lm1);
            float f0 = exp2f(rmax[u][0] - nm0), f1 = exp2f(rmax[u][1] - nm1);
            rmax[u][0] = nm0; rmax[u][1] = nm1;
            float ls0 = 0.f, ls1 = 0.f;
#pragma unroll
            for (int nt = 0; nt < 8; nt++) {
                float p00 = exp2f(s[u][nt][0] - nm0);
                float p01 = exp2f(s[u][nt][1] - nm0);
                float p10 = exp2f(s[u][nt][2] - nm1);
                float p11 = exp2f(s[u][nt][3] - nm1);
                ls0 += p00 + p01; ls1 += p10 + p11;
                sPh[(rb + r    ) * 36 + nt * 4 + t] = __floats2half2_rn(p00, p01);
                sPh[(rb + r + 8) * 36 + nt * 4 + t] = __floats2half2_rn(p10, p11);
            }
            ls0 += __shfl_xor_sync(0xffffffffu, ls0, 1);
            ls0 += __shfl_xor_sync(0xffffffffu, ls0, 2);
            ls1 += __shfl_xor_sync(0xffffffffu, ls1, 1);
            ls1 += __shfl_xor_sync(0xffffffffu, ls1, 2);
            rsum[u][0] = rsum[u][0] * f0 + ls0;
            rsum[u][1] = rsum[u][1] * f1 + ls1;
#pragma unroll
            for (int nt = 0; nt < 8; nt++) {
                out[u][nt][0] *= f0; out[u][nt][1] *= f0;
                out[u][nt][2] *= f1; out[u][nt][3] *= f1;
            }
        }
        __syncwarp();      // own P rows visible to own lanes

        // ---- P @ V ----
#pragma unroll
        for (int ks = 0; ks < 4; ks++) {
            int kb = ks * 8;
            uint32_t a[2][4];
#pragma unroll
            for (int u = 0; u < 2; u++) {
                int rb = qb + u * 16;
                a[u][0] = sP[(rb + r    ) * 36 + kb + t    ];
                a[u][1] = sP[(rb + r + 8) * 36 + kb + t    ];
                a[u][2] = sP[(rb + r    ) * 36 + kb + t + 4];
                a[u][3] = sP[(rb + r + 8) * 36 + kb + t + 4];
            }
#pragma unroll
            for (int nt = 0; nt < 8; nt++) {
                uint32_t b0 = sVtb[(nt * 8 + r) * 36 + kb + t    ];
                uint32_t b1 = sVtb[(nt * 8 + r) * 36 + kb + t + 4];
                mma_f16(out[0][nt], a[0][0], a[0][1], a[0][2], a[0][3], b0, b1);
                mma_f16(out[1][nt], a[1][0], a[1][1], a[1][2], a[1][3], b0, b1);
            }
        }
        __syncthreads();   // buffer reuse protection
    }

    // ---- epilogue ----
    float* dst = g_ao + ((size_t)b * N_ + n0) * INNER_ + h * 64;
#pragma unroll
    for (int u = 0; u < 2; u++) {
        int rb = qb + u * 16;
        float inv0 = 1.f / rsum[u][0], inv1 = 1.f / rsum[u][1];
#pragma unroll
        for (int nt = 0; nt < 8; nt++) {
            int col = nt * 8 + 2 * t;
            *(float2*)&dst[(size_t)(rb + r    ) * INNER_ + col] =
                make_float2(out[u][nt][0] * inv0, out[u][nt][1] * inv0);
            *(float2*)&dst[(size_t)(rb + r + 8) * INNER_ + col] =
                make_float2(out[u][nt][2] * inv1, out[u][nt][3] * inv1);
        }
    }
}

// ---------------- K5: output projection, tf32 mma, 128x64 blocks ----------------
#define OPROJ_SMEM ((128 * 68 + 64 * 68) * 4)
__global__ void __launch_bounds__(256, 2) k_oproj(const float* __restrict__ wo,
                                                  const float* __restrict__ bo,
                                                  float* __restrict__ out) {
    extern __shared__ float smemf[];
    float (*sA)[68] = (float(*)[68])(smemf);
    float (*sW)[68] = (float(*)[68])(smemf + 128 * 68);
    int row0 = blockIdx.x * 128;
    int o0   = blockIdx.y * 64;
    int tid  = threadIdx.x;
    int wid  = tid >> 5, lane = tid & 31;
    int r    = lane >> 2, t = lane & 3;
    int qb   = wid * 16;

    float s[8][4];
#pragma unroll
    for (int nt = 0; nt < 8; nt++)
#pragma unroll
        for (int c = 0; c < 4; c++) s[nt][c] = 0.f;

    for (int c0 = 0; c0 < INNER_; c0 += 64) {
#pragma unroll
        for (int it = 0; it < 8; it++) {
            int idx = tid + it * 256;
            int rr = idx >> 4, c4 = (idx & 15) * 4;
            float4 a4 = *(const float4*)&g_ao[(size_t)(row0 + rr) * INNER_ + c0 + c4];
            sA[rr][c4 + 0] = __uint_as_float(f2tf32(a4.x));
            sA[rr][c4 + 1] = __uint_as_float(f2tf32(a4.y));
            sA[rr][c4 + 2] = __uint_as_float(f2tf32(a4.z));
            sA[rr][c4 + 3] = __uint_as_float(f2tf32(a4.w));
        }
#pragma unroll
        for (int it = 0; it < 4; it++) {
            int idx = tid + it * 256;
            int rr = idx >> 4, c4 = (idx & 15) * 4;
            float4 w4 = *(const float4*)&wo[(size_t)(o0 + rr) * INNER_ + c0 + c4];
            sW[rr][c4 + 0] = __uint_as_float(f2tf32(w4.x));
            sW[rr][c4 + 1] = __uint_as_float(f2tf32(w4.y));
            sW[rr][c4 + 2] = __uint_as_float(f2tf32(w4.z));
            sW[rr][c4 + 3] = __uint_as_float(f2tf32(w4.w));
        }
        __syncthreads();
#pragma unroll
        for (int ks = 0; ks < 8; ks++) {
            int k0 = ks * 8;
            uint32_t a0 = __float_as_uint(sA[qb + r    ][k0 + t    ]);
            uint32_t a1 = __float_as_uint(sA[qb + r + 8][k0 + t    ]);
            uint32_t a2 = __float_as_uint(sA[qb + r    ][k0 + t + 4]);
            uint32_t a3 = __float_as_uint(sA[qb + r + 8][k0 + t + 4]);
#pragma unroll
            for (int nt = 0; nt < 8; nt++) {
                uint32_t b0 = __float_as_uint(sW[nt * 8 + r][k0 + t    ]);
                uint32_t b1 = __float_as_uint(sW[nt * 8 + r][k0 + t + 4]);
                mma_tf32(s[nt], a0, a1, a2, a3, b0, b1);
            }
        }
        __syncthreads();
    }

#pragma unroll
    for (int nt = 0; nt < 8; nt++) {
        int col = nt * 8 + 2 * t;
        int o = o0 + col;
        float b0 = bo[o], b1 = bo[o + 1];
        *(float2*)&out[(size_t)(row0 + qb + r    ) * D_ + o] =
            make_float2(s[nt][0] + b0, s[nt][1] + b1);
        *(float2*)&out[(size_t)(row0 + qb + r + 8) * D_ + o] =
            make_float2(s[nt][2] + b0, s[nt][3] + b1);
    }
}

// ---------------- launch ----------------
extern "C" void kernel_launch(void* const* d_in, const int* in_sizes, int n_in,
                              void* d_out, int out_size) {
    const float* x      = (const float*)d_in[0];
    const float* prev_x = (const float*)d_in[1];
    const float* wq     = (const float*)d_in[2];
    const float* wk     = (const float*)d_in[3];
    const float* wv     = (const float*)d_in[4];
    const float* wo     = (const float*)d_in[5];
    const float* bo     = (const float*)d_in[6];
    const float* w_off1 = (const float*)d_in[7];
    const float* b_off1 = (const float*)d_in[8];
    const float* w_off2 = (const float*)d_in[9];
    float* out = (float*)d_out;

    cudaFuncSetAttribute(k_attn,  cudaFuncAttributeMaxDynamicSharedMemorySize, ATTN_SMEM);
    cudaFuncSetAttribute(k_oproj, cudaFuncAttributeMaxDynamicSharedMemorySize, OPROJ_SMEM);

    k_qproj  <<<dim3(B_ * N_ / 64, G_), 256>>>(x, prev_x, wq);
    k_offsets<<<(B_ * G_ * M_) / 4, 256>>>(w_off1, b_off1, w_off2);
    k_kv     <<<(B_ * G_ * M_) / 32, 256>>>(prev_x, wk, wv);
    k_attn   <<<B_ * H_ * (N_ / 128), 128, ATTN_SMEM>>>();
    k_oproj  <<<dim3((B_ * N_) / 128, D_ / 64), 256, OPROJ_SMEM>>>(wo, bo, out);
}

// round 12
// speedup vs baseline: 17.8129x; 1.1277x over previous
#include <cuda_runtime.h>
#include <cuda_fp16.h>
#include <math.h>
#include <stdint.h>

// ---------------- constants (problem shapes are fixed) ----------------
#define B_   4
#define N_   4096
#define D_   256
#define H_   8
#define G_   8
#define DH_  64
#define INNER_ 512
#define M_   1024
#define KS_  6
#define QSCALE 0.1803368801111f   // 0.125 * log2(e)

// ---------------- fp16 mma helper ----------------
__device__ __forceinline__ void mma_f16(float* d,
                                        uint32_t a0, uint32_t a1, uint32_t a2, uint32_t a3,
                                        uint32_t b0, uint32_t b1) {
    asm("mma.sync.aligned.m16n8k16.row.col.f32.f16.f16.f32 "
        "{%0,%1,%2,%3}, {%4,%5,%6,%7}, {%8,%9}, {%0,%1,%2,%3};"
        : "+f"(d[0]), "+f"(d[1]), "+f"(d[2]), "+f"(d[3])
        : "r"(a0), "r"(a1), "r"(a2), "r"(a3), "r"(b0), "r"(b1));
}
__device__ __forceinline__ void ldm_x4(uint32_t& r0, uint32_t& r1, uint32_t& r2, uint32_t& r3,
                                       uint32_t addr) {
    asm volatile("ldmatrix.sync.aligned.m8n8.x4.shared.b16 {%0,%1,%2,%3}, [%4];"
                 : "=r"(r0), "=r"(r1), "=r"(r2), "=r"(r3) : "r"(addr));
}
__device__ __forceinline__ void stm_x4(uint32_t addr, uint32_t r0, uint32_t r1,
                                       uint32_t r2, uint32_t r3) {
    asm volatile("stmatrix.sync.aligned.m8n8.x4.shared.b16 [%0], {%1,%2,%3,%4};"
                 :: "r"(addr), "r"(r0), "r"(r1), "r"(r2), "r"(r3));
}
// pack two f32 into one u32 of f16x2 (lo, hi) — single CVT
__device__ __forceinline__ uint32_t pack_h2(float lo, float hi) {
    uint32_t r;
    asm("cvt.rn.f16x2.f32 %0, %1, %2;" : "=r"(r) : "f"(hi), "f"(lo));
    return r;
}
__device__ __forceinline__ uint32_t cvta_smem(const void* p) {
    return (uint32_t)__cvta_generic_to_shared(p);
}
#define CP_A16(dst_u32, src_ptr) \
    asm volatile("cp.async.cg.shared.global [%0], [%1], 16;" :: "r"(dst_u32), "l"(src_ptr))

// ---------------- scratch ----------------
__device__ float  g_q  [B_ * N_ * INNER_];      // fp32 q (offsets path)
__device__ __half g_qh [B_ * N_ * INNER_];      // fp16 q, pre-scaled by QSCALE
__device__ float  g_pos[B_ * G_ * M_];
__device__ __half g_kh [B_ * M_ * INNER_];
__device__ __half g_vth[B_ * H_ * DH_ * M_];    // transposed V: [b][h][d][m]
__device__ __half g_aoh[B_ * N_ * INNER_];      // fp16 attention output

// ---------------- K1: q = grouped conv1x1, GEMM-tiled per group ----------------
__global__ __launch_bounds__(256) void k_qproj(const float* __restrict__ x,
                                               const float* __restrict__ px,
                                               const float* __restrict__ wq) {
    __shared__ float sIn[64][68];
    __shared__ float sW [64][68];
    int tok0 = blockIdx.x * 64;
    int g    = blockIdx.y;
    int tid  = threadIdx.x;
    int ty = tid >> 4, tx = tid & 15;

    const float* src = (g < 4) ? px : x;
    int cb = (g & 3) * 64;

#pragma unroll
    for (int it = 0; it < 4; it++) {
        int idx = tid + it * 256;
        int r = idx >> 4, c4 = (idx & 15) * 4;
        *(float4*)&sIn[r][c4] = *(const float4*)&src[(size_t)(tok0 + r) * D_ + cb + c4];
        *(float4*)&sW [r][c4] = *(const float4*)&wq [(size_t)(g * 64 + r) * 64 + c4];
    }
    __syncthreads();

    float acc[4][4];
#pragma unroll
    for (int i = 0; i < 4; i++)
#pragma unroll
        for (int j = 0; j < 4; j++) acc[i][j] = 0.f;

#pragma unroll
    for (int d0 = 0; d0 < 64; d0 += 4) {
        float4 av[4], wv[4];
#pragma unroll
        for (int i = 0; i < 4; i++) av[i] = *(const float4*)&sIn[ty + 16 * i][d0];
#pragma unroll
        for (int j = 0; j < 4; j++) wv[j] = *(const float4*)&sW[tx + 16 * j][d0];
#pragma unroll
        for (int i = 0; i < 4; i++)
#pragma unroll
            for (int j = 0; j < 4; j++) {
                acc[i][j] = fmaf(av[i].x, wv[j].x, acc[i][j]);
                acc[i][j] = fmaf(av[i].y, wv[j].y, acc[i][j]);
                acc[i][j] = fmaf(av[i].z, wv[j].z, acc[i][j]);
                acc[i][j] = fmaf(av[i].w, wv[j].w, acc[i][j]);
            }
    }
#pragma unroll
    for (int i = 0; i < 4; i++)
#pragma unroll
        for (int j = 0; j < 4; j++) {
            size_t o = (size_t)(tok0 + ty + 16 * i) * INNER_ + g * 64 + tx + 16 * j;
            g_q [o] = acc[i][j];
            g_qh[o] = __float2half_rn(acc[i][j] * QSCALE);
        }
}

// ---------------- K2: offsets -> sampling positions ----------------
__global__ __launch_bounds__(256) void k_offsets(const float* __restrict__ w1,
                                                 const float* __restrict__ b1,
                                                 const float* __restrict__ w2) {
    __shared__ float red[8];
    int tid = threadIdx.x;
    int p = blockIdx.x * 4 + (tid >> 6);
    int c = tid & 63;
    int bc = p >> 10, m = p & (M_ - 1);
    int b = bc >> 3, g = bc & 7;
    const float* qbase = g_q + (size_t)b * N_ * INNER_ + g * 64 + c;

    float h = b1[c];
    int n0 = 4 * m - 1;
#pragma unroll
    for (int k = 0; k < KS_; k++) {
        int n = n0 + k;
        if (n >= 0 && n < N_) h = fmaf(qbase[(size_t)n * INNER_], w1[c * KS_ + k], h);
    }
    float ge  = 0.5f * h * (1.f + erff(h * 0.70710678118654752f));
    float val = ge * w2[c];
#pragma unroll
    for (int o = 16; o > 0; o >>= 1) val += __shfl_xor_sync(0xffffffffu, val, o);
    if ((tid & 31) == 0) red[tid >> 5] = val;
    __syncthreads();
    if (tid < 4) {
        float off = tanhf(red[2 * tid] + red[2 * tid + 1]) * 4.0f;
        int pp = blockIdx.x * 4 + tid;
        int mm = pp & (M_ - 1);
        g_pos[pp] = ((float)mm + off) * ((float)N_ / (float)(M_ - 1)) - 0.5f;
    }
}

// ---------------- K3: gather + k/v conv1x1; K fp16, V fp16 transposed ----------------
__global__ __launch_bounds__(256) void k_kv(const float* __restrict__ px,
                                            const float* __restrict__ wk,
                                            const float* __restrict__ wv) {
    __shared__ float skv[32][33];
    __shared__ float sW [128][33];
    int blk = blockIdx.x;
    int bc  = blk >> 5;
    int m0  = (blk & 31) * 32;
    int b = bc >> 3, g = bc & 7;
    int tid = threadIdx.x;

#pragma unroll
    for (int it = 0; it < 16; it++) {
        int idx = tid + it * 256;
        int row = idx >> 5, d = idx & 31;
        const float* w = (row < 64) ? wk : wv;
        sW[row][d] = w[(size_t)(g * 64 + (row & 63)) * 32 + d];
    }

#pragma unroll
    for (int it = 0; it < 4; it++) {
        int idx = tid + it * 256;
        int m = idx & 31, ch = idx >> 5;
        float pos = g_pos[bc * M_ + m0 + m];
        float fp  = floorf(pos);
        int   i0  = (int)fp;
        float w1f = pos - fp;
        const float* base = px + (size_t)b * N_ * D_ + g * 32 + ch;
        float v0 = (i0 >= 0     && i0     < N_) ? base[(size_t)i0 * D_]       : 0.f;
        float v1 = (i0 + 1 >= 0 && i0 + 1 < N_) ? base[(size_t)(i0 + 1) * D_] : 0.f;
        skv[ch][m] = v0 * (1.f - w1f) + v1 * w1f;
    }
    __syncthreads();

#pragma unroll
    for (int u = 0; u < 8; u++) {
        int idx = tid + u * 256;
        int o = idx & 63, msub = idx >> 6;
        float acc = 0.f;
#pragma unroll
        for (int d = 0; d < 32; d++) acc = fmaf(skv[d][msub], sW[o][d], acc);
        g_kh[((size_t)b * M_ + m0 + msub) * INNER_ + g * 64 + o] = __float2half_rn(acc);
    }
#pragma unroll
    for (int u = 0; u < 8; u++) {
        int idx = tid + u * 256;
        int m = idx & 31, o = idx >> 5;
        float acc = 0.f;
#pragma unroll
        for (int d = 0; d < 32; d++) acc = fmaf(skv[d][m], sW[64 + o][d], acc);
        g_vth[((size_t)(b * 8 + g) * 64 + o) * M_ + m0 + m] = __float2half_rn(acc);
    }
}

// ---------------- K4: flash attention, fp16 mma + ldmatrix/stmatrix ----------------
// smem u32 (stride 36 = 72 halves): Q[128*36] | K 2x[64*36] | Vt 2x[64*36] | P[128*36]
#define ATTN_SMEM ((128 * 36 + 4 * 64 * 36 + 128 * 36) * 4)
__global__ void __launch_bounds__(128, 3) k_attn() {
    int blk = blockIdx.x;            // b*256 + h*32 + qt
    int qt = blk & 31;
    int h  = (blk >> 5) & 7;
    int b  = blk >> 8;
    int n0 = qt << 7;

    extern __shared__ uint32_t smem[];
    uint32_t* sQ  = smem;
    uint32_t* sK  = smem + 128 * 36;
    uint32_t* sVt = smem + 128 * 36 + 2 * 64 * 36;
    uint32_t* sP  = smem + 128 * 36 + 4 * 64 * 36;

    int tid  = threadIdx.x;
    int wid  = tid >> 5, lane = tid & 31;
    int qb   = wid * 32;

    const __half* qsrc   = g_qh  + ((size_t)b * N_ + n0) * INNER_ + h * 64;
    const __half* kbase  = g_kh  + ((size_t)b * M_) * INNER_ + h * 64;
    const __half* vtbase = g_vth + ((size_t)(b * 8 + h) * 64) * M_;

    // ---- stage Q ----
#pragma unroll
    for (int it = 0; it < 8; it++) {
        int idx = tid + it * 128;
        int rr = idx >> 3, c = idx & 7;
        *(uint4*)&sQ[rr * 36 + c * 4] = *(const uint4*)(qsrc + (size_t)rr * INNER_ + c * 8);
    }

    // ---- ldmatrix/stmatrix lane addresses ----
    int arow = lane & 15;
    int acol = (lane & 16) >> 2;                 // 0 or 4 u32
    int brow = (lane & 7) | ((lane >> 1) & 8);
    int bcol = (lane & 8) >> 1;                  // 0 or 4 u32
    uint32_t aQ  = cvta_smem(sQ)  + (uint32_t)(((qb + arow) * 36 + acol) * 4);
    uint32_t aP  = cvta_smem(sP)  + (uint32_t)(((qb + arow) * 36 + acol) * 4);
    uint32_t stP = aP;
    uint32_t bK  = cvta_smem(sK)  + (uint32_t)((brow * 36 + bcol) * 4);
    uint32_t bV  = cvta_smem(sVt) + (uint32_t)((brow * 36 + bcol) * 4);

    uint32_t sKaddr = cvta_smem(sK);
    uint32_t sVaddr = cvta_smem(sVt);
    auto load_tile = [&](int kt, int buf) {
        int m0 = kt << 6;
#pragma unroll
        for (int it = 0; it < 4; it++) {
            int idx = tid + it * 128;
            int rr = idx >> 3, c = idx & 7;
            CP_A16(sKaddr + (uint32_t)(buf * 64 * 36 + rr * 36 + c * 4) * 4,
                   kbase + (size_t)(m0 + rr) * INNER_ + c * 8);
        }
#pragma unroll
        for (int it = 0; it < 4; it++) {
            int idx = tid + it * 128;
            int rr = idx >> 3, c = idx & 7;
            CP_A16(sVaddr + (uint32_t)(buf * 64 * 36 + rr * 36 + c * 4) * 4,
                   vtbase + (size_t)rr * M_ + m0 + c * 8);
        }
    };

    float out[2][8][4];
#pragma unroll
    for (int u = 0; u < 2; u++)
#pragma unroll
        for (int nt = 0; nt < 8; nt++)
#pragma unroll
            for (int c = 0; c < 4; c++) out[u][nt][c] = 0.f;
    float rmax[2][2], rsum[2][2];
#pragma unroll
    for (int u = 0; u < 2; u++) { rmax[u][0] = rmax[u][1] = -1e30f; rsum[u][0] = rsum[u][1] = 0.f; }

    load_tile(0, 0);
    asm volatile("cp.async.commit_group;");

    for (int kt = 0; kt < 16; kt++) {
        int buf = kt & 1;
        if (kt < 15) {
            load_tile(kt + 1, buf ^ 1);
            asm volatile("cp.async.commit_group;");
            asm volatile("cp.async.wait_group 1;");
        } else {
            asm volatile("cp.async.wait_group 0;");
        }
        __syncthreads();

        uint32_t bufoff = (uint32_t)(buf * 64 * 36 * 4);

        // ---- QK^T ----
        float s[2][8][4];
#pragma unroll
        for (int u = 0; u < 2; u++)
#pragma unroll
            for (int nt = 0; nt < 8; nt++)
#pragma unroll
                for (int c = 0; c < 4; c++) s[u][nt][c] = 0.f;

#pragma unroll
        for (int ks = 0; ks < 4; ks++) {
            uint32_t a[2][4];
            ldm_x4(a[0][0], a[0][1], a[0][2], a[0][3], aQ + ks * 32);
            ldm_x4(a[1][0], a[1][1], a[1][2], a[1][3], aQ + 2304 + ks * 32);
#pragma unroll
            for (int ntp = 0; ntp < 4; ntp++) {
                uint32_t b00, b01, b10, b11;
                ldm_x4(b00, b01, b10, b11, bK + bufoff + ntp * 2304 + ks * 32);
                mma_f16(s[0][2 * ntp    ], a[0][0], a[0][1], a[0][2], a[0][3], b00, b01);
                mma_f16(s[1][2 * ntp    ], a[1][0], a[1][1], a[1][2], a[1][3], b00, b01);
                mma_f16(s[0][2 * ntp + 1], a[0][0], a[0][1], a[0][2], a[0][3], b10, b11);
                mma_f16(s[1][2 * ntp + 1], a[1][0], a[1][1], a[1][2], a[1][3], b10, b11);
            }
        }

        // ---- online softmax (exp2 domain) + P via stmatrix ----
#pragma unroll
        for (int u = 0; u < 2; u++) {
            float lm0 = -1e30f, lm1 = -1e30f;
#pragma unroll
            for (int nt = 0; nt < 8; nt++) {
                lm0 = fmaxf(lm0, fmaxf(s[u][nt][0], s[u][nt][1]));
                lm1 = fmaxf(lm1, fmaxf(s[u][nt][2], s[u][nt][3]));
            }
            lm0 = fmaxf(lm0, __shfl_xor_sync(0xffffffffu, lm0, 1));
            lm0 = fmaxf(lm0, __shfl_xor_sync(0xffffffffu, lm0, 2));
            lm1 = fmaxf(lm1, __shfl_xor_sync(0xffffffffu, lm1, 1));
            lm1 = fmaxf(lm1, __shfl_xor_sync(0xffffffffu, lm1, 2));
            float nm0 = fmaxf(rmax[u][0], lm0), nm1 = fmaxf(rmax[u][1], lm1);
            float f0 = exp2f(rmax[u][0] - nm0), f1 = exp2f(rmax[u][1] - nm1);
            rmax[u][0] = nm0; rmax[u][1] = nm1;
            float ls0 = 0.f, ls1 = 0.f;
#pragma unroll
            for (int ntp = 0; ntp < 4; ntp++) {
                float pa0 = exp2f(s[u][2*ntp][0] - nm0);
                float pa1 = exp2f(s[u][2*ntp][1] - nm0);
                float pa2 = exp2f(s[u][2*ntp][2] - nm1);
                float pa3 = exp2f(s[u][2*ntp][3] - nm1);
                float pb0 = exp2f(s[u][2*ntp+1][0] - nm0);
                float pb1 = exp2f(s[u][2*ntp+1][1] - nm0);
                float pb2 = exp2f(s[u][2*ntp+1][2] - nm1);
                float pb3 = exp2f(s[u][2*ntp+1][3] - nm1);
                ls0 += pa0 + pa1 + pb0 + pb1;
                ls1 += pa2 + pa3 + pb2 + pb3;
                uint32_t q0 = pack_h2(pa0, pa1);
                uint32_t q1 = pack_h2(pa2, pa3);
                uint32_t q2 = pack_h2(pb0, pb1);
                uint32_t q3 = pack_h2(pb2, pb3);
                stm_x4(stP + (uint32_t)(u * 2304 + ntp * 32), q0, q1, q2, q3);
            }
            ls0 += __shfl_xor_sync(0xffffffffu, ls0, 1);
            ls0 += __shfl_xor_sync(0xffffffffu, ls0, 2);
            ls1 += __shfl_xor_sync(0xffffffffu, ls1, 1);
            ls1 += __shfl_xor_sync(0xffffffffu, ls1, 2);
            rsum[u][0] = rsum[u][0] * f0 + ls0;
            rsum[u][1] = rsum[u][1] * f1 + ls1;
#pragma unroll
            for (int nt = 0; nt < 8; nt++) {
                out[u][nt][0] *= f0; out[u][nt][1] *= f0;
                out[u][nt][2] *= f1; out[u][nt][3] *= f1;
            }
        }
        __syncwarp();

        // ---- P @ V ----
#pragma unroll
        for (int ks = 0; ks < 4; ks++) {
            uint32_t a[2][4];
            ldm_x4(a[0][0], a[0][1], a[0][2], a[0][3], aP + ks * 32);
            ldm_x4(a[1][0], a[1][1], a[1][2], a[1][3], aP + 2304 + ks * 32);
#pragma unroll
            for (int ntp = 0; ntp < 4; ntp++) {
                uint32_t b00, b01, b10, b11;
                ldm_x4(b00, b01, b10, b11, bV + bufoff + ntp * 2304 + ks * 32);
                mma_f16(out[0][2 * ntp    ], a[0][0], a[0][1], a[0][2], a[0][3], b00, b01);
                mma_f16(out[1][2 * ntp    ], a[1][0], a[1][1], a[1][2], a[1][3], b00, b01);
                mma_f16(out[0][2 * ntp + 1], a[0][0], a[0][1], a[0][2], a[0][3], b10, b11);
                mma_f16(out[1][2 * ntp + 1], a[1][0], a[1][1], a[1][2], a[1][3], b10, b11);
            }
        }
        __syncthreads();
    }

    // ---- epilogue: fp16 output ----
    int r = lane >> 2, t = lane & 3;
    __half* dsth = g_aoh + ((size_t)b * N_ + n0) * INNER_ + h * 64;
#pragma unroll
    for (int u = 0; u < 2; u++) {
        int rb = qb + u * 16;
        float inv0 = 1.f / rsum[u][0], inv1 = 1.f / rsum[u][1];
#pragma unroll
        for (int nt = 0; nt < 8; nt++) {
            int col = nt * 8 + 2 * t;
            uint32_t p0 = pack_h2(out[u][nt][0] * inv0, out[u][nt][1] * inv0);
            uint32_t p1 = pack_h2(out[u][nt][2] * inv1, out[u][nt][3] * inv1);
            *(uint32_t*)(dsth + (size_t)(rb + r    ) * INNER_ + col) = p0;
            *(uint32_t*)(dsth + (size_t)(rb + r + 8) * INNER_ + col) = p1;
        }
    }
}

// ---------------- K5: output projection, fp16 mma + ldmatrix ----------------
// smem u32 (stride 36): A[128*36] | W[64*36]
#define OPROJ_SMEM ((128 * 36 + 64 * 36) * 4)
__global__ void __launch_bounds__(256, 3) k_oproj(const float* __restrict__ wo,
                                                  const float* __restrict__ bo,
                                                  float* __restrict__ out) {
    extern __shared__ uint32_t smem[];
    uint32_t* sA = smem;
    uint32_t* sW = smem + 128 * 36;
    int row0 = blockIdx.x * 128;
    int o0   = blockIdx.y * 64;
    int tid  = threadIdx.x;
    int wid  = tid >> 5, lane = tid & 31;
    int r    = lane >> 2, t = lane & 3;
    int qb   = wid * 16;

    int arow = lane & 15;
    int acol = (lane & 16) >> 2;
    int brow = (lane & 7) | ((lane >> 1) & 8);
    int bcol = (lane & 8) >> 1;
    uint32_t aA = cvta_smem(sA) + (uint32_t)(((qb + arow) * 36 + acol) * 4);
    uint32_t bW = cvta_smem(sW) + (uint32_t)((brow * 36 + bcol) * 4);

    float s[8][4];
#pragma unroll
    for (int nt = 0; nt < 8; nt++)
#pragma unroll
        for (int c = 0; c < 4; c++) s[nt][c] = 0.f;

    for (int c0 = 0; c0 < INNER_; c0 += 64) {
        // stage A (fp16 already)
#pragma unroll
        for (int it = 0; it < 4; it++) {
            int idx = tid + it * 256;
            int rr = idx >> 3, c = idx & 7;
            *(uint4*)&sA[rr * 36 + c * 4] =
                *(const uint4*)(g_aoh + (size_t)(row0 + rr) * INNER_ + c0 + c * 8);
        }
        // stage W (convert fp32 -> fp16)
#pragma unroll
        for (int it = 0; it < 4; it++) {
            int idx = tid + it * 256;
            int rr = idx >> 4, c = idx & 15;
            float4 w4 = *(const float4*)&wo[(size_t)(o0 + rr) * INNER_ + c0 + c * 4];
            sW[rr * 36 + c * 2    ] = pack_h2(w4.x, w4.y);
            sW[rr * 36 + c * 2 + 1] = pack_h2(w4.z, w4.w);
        }
        __syncthreads();
#pragma unroll
        for (int ks = 0; ks < 4; ks++) {
            uint32_t a0, a1, a2, a3;
            ldm_x4(a0, a1, a2, a3, aA + ks * 32);
#pragma unroll
            for (int ntp = 0; ntp < 4; ntp++) {
                uint32_t b00, b01, b10, b11;
                ldm_x4(b00, b01, b10, b11, bW + ntp * 2304 + ks * 32);
                mma_f16(s[2 * ntp    ], a0, a1, a2, a3, b00, b01);
                mma_f16(s[2 * ntp + 1], a0, a1, a2, a3, b10, b11);
            }
        }
        __syncthreads();
    }

#pragma unroll
    for (int nt = 0; nt < 8; nt++) {
        int col = nt * 8 + 2 * t;
        int o = o0 + col;
        float b0 = bo[o], b1 = bo[o + 1];
        *(float2*)&out[(size_t)(row0 + qb + r    ) * D_ + o] =
            make_float2(s[nt][0] + b0, s[nt][1] + b1);
        *(float2*)&out[(size_t)(row0 + qb + r + 8) * D_ + o] =
            make_float2(s[nt][2] + b0, s[nt][3] + b1);
    }
}

// ---------------- launch ----------------
extern "C" void kernel_launch(void* const* d_in, const int* in_sizes, int n_in,
                              void* d_out, int out_size) {
    const float* x      = (const float*)d_in[0];
    const float* prev_x = (const float*)d_in[1];
    const float* wq     = (const float*)d_in[2];
    const float* wk     = (const float*)d_in[3];
    const float* wv     = (const float*)d_in[4];
    const float* wo     = (const float*)d_in[5];
    const float* bo     = (const float*)d_in[6];
    const float* w_off1 = (const float*)d_in[7];
    const float* b_off1 = (const float*)d_in[8];
    const float* w_off2 = (const float*)d_in[9];
    float* out = (float*)d_out;

    cudaFuncSetAttribute(k_attn,  cudaFuncAttributeMaxDynamicSharedMemorySize, ATTN_SMEM);
    cudaFuncSetAttribute(k_oproj, cudaFuncAttributeMaxDynamicSharedMemorySize, OPROJ_SMEM);

    k_qproj  <<<dim3(B_ * N_ / 64, G_), 256>>>(x, prev_x, wq);
    k_offsets<<<(B_ * G_ * M_) / 4, 256>>>(w_off1, b_off1, w_off2);
    k_kv     <<<(B_ * G_ * M_) / 32, 256>>>(prev_x, wk, wv);
    k_attn   <<<B_ * H_ * (N_ / 128), 128, ATTN_SMEM>>>();
    k_oproj  <<<dim3((B_ * N_) / 128, D_ / 64), 256, OPROJ_SMEM>>>(wo, bo, out);
}